// round 1
// baseline (speedup 1.0000x reference)
#include <cuda_runtime.h>
#include <math.h>

// ---------------- problem constants ----------------
#define BATCH 64
#define HDIM 56
#define WDIM 56
#define CDIM 128
#define NHEAD 4
#define DHEAD 32
#define WSZ 7
#define SHIFT 3
#define NTOK 49              // tokens per window
#define NWIN 64              // windows per image (8x8)
#define NWB (BATCH * NWIN)   // 4096
#define MROWS (NWB * NTOK)   // 200704 == B*H*W
#define HID 512

// ---------------- scratch (device globals; no allocation allowed) ----------------
__device__ float g_xw[(size_t)MROWS * CDIM];        // LN1 + windowed
__device__ float g_qkv[(size_t)MROWS * 3 * CDIM];   // qkv
__device__ float g_attn[(size_t)MROWS * CDIM];      // attention out (window layout)
__device__ float g_x1[(size_t)MROWS * CDIM];        // post-attention residual
__device__ float g_xn2[(size_t)MROWS * CDIM];       // LN2 out
__device__ float g_h[(size_t)MROWS * HID];          // MLP hidden

// ---------------- LayerNorm (optionally fused with shift + window partition gather) ---
// GATHER==1: output row r is in window layout; source token is gathered from the
// rolled image:  src = xn[(wh*7+i+SHIFT)%H, (ww*7+j+SHIFT)%W]
template <int GATHER>
__global__ void ln_kernel(const float* __restrict__ x, const float* __restrict__ gamma,
                          const float* __restrict__ beta, float* __restrict__ out) {
    int token = blockIdx.x * 8 + (threadIdx.x >> 5);
    int lane = threadIdx.x & 31;
    long srow;
    if (GATHER) {
        int widx = token / NTOK, n = token % NTOK;
        int b = widx >> 6, wi = widx & 63;
        int wh = wi >> 3, ww = wi & 7;
        int i = n / 7, j = n - i * 7;
        int sh = wh * 7 + i + SHIFT; if (sh >= HDIM) sh -= HDIM;
        int sw = ww * 7 + j + SHIFT; if (sw >= WDIM) sw -= WDIM;
        srow = (long)b * (HDIM * WDIM) + sh * WDIM + sw;
    } else {
        srow = token;
    }
    float4 v = ((const float4*)(x + srow * (long)CDIM))[lane];
    float s = v.x + v.y + v.z + v.w;
    float sq = v.x * v.x + v.y * v.y + v.z * v.z + v.w * v.w;
    #pragma unroll
    for (int o = 16; o; o >>= 1) {
        s  += __shfl_xor_sync(0xFFFFFFFFu, s, o);
        sq += __shfl_xor_sync(0xFFFFFFFFu, sq, o);
    }
    float mu = s * (1.0f / 128.0f);
    float var = sq * (1.0f / 128.0f) - mu * mu;
    float inv = rsqrtf(var + 1e-5f);
    float4 g = ((const float4*)gamma)[lane];
    float4 b4 = ((const float4*)beta)[lane];
    float4 r;
    r.x = (v.x - mu) * inv * g.x + b4.x;
    r.y = (v.y - mu) * inv * g.y + b4.y;
    r.z = (v.z - mu) * inv * g.z + b4.z;
    r.w = (v.w - mu) * inv * g.w + b4.w;
    ((float4*)(out + (long)token * CDIM))[lane] = r;
}

// ---------------- tiled SGEMM:  out[M,ld] = A[rowmap(M),K] @ W[N,K]^T + bias (+epi) ----
// BM=128, BN=128, BK=16, 256 threads, 8x8 per thread.
// GATHER==1: A row for destination token r is the window-reverse + unshift source row.
// EPI: 0 = plain, 1 = exact GELU, 2 = + resid[r*128 + c]
template <int GATHER, int EPI>
__global__ void __launch_bounds__(256)
gemm_kernel(const float* __restrict__ A, const float* __restrict__ W,
            const float* __restrict__ bias, const float* __restrict__ resid,
            float* __restrict__ out, int K, int ldout) {
    __shared__ float As[16][128];
    __shared__ float Bs[16][128];
    __shared__ int rowmap[128];
    const int tid = threadIdx.x;
    const int blockRow = blockIdx.x, blockCol = blockIdx.y;

    if (tid < 128) {
        int r = blockRow * 128 + tid;
        if (GATHER) {
            int b = r / (HDIM * WDIM);
            int l = r - b * (HDIM * WDIM);
            int h = l / WDIM, w = l - h * WDIM;
            int sh = h - SHIFT; if (sh < 0) sh += HDIM;
            int sw = w - SHIFT; if (sw < 0) sw += WDIM;
            int wh = sh / 7, i = sh - wh * 7;
            int ww = sw / 7, j = sw - ww * 7;
            rowmap[tid] = ((b * 64 + wh * 8 + ww) * 49 + i * 7 + j);
        } else {
            rowmap[tid] = r;
        }
    }
    __syncthreads();

    const int tx = tid & 15, ty = tid >> 4;
    float acc[8][8];
    #pragma unroll
    for (int i = 0; i < 8; i++)
        #pragma unroll
        for (int j = 0; j < 8; j++) acc[i][j] = 0.0f;

    for (int k0 = 0; k0 < K; k0 += 16) {
        #pragma unroll
        for (int it = 0; it < 2; it++) {
            int f = tid + it * 256;            // 0..511 float4 slots
            int row = f >> 2, c4 = f & 3;
            float4 v = *(const float4*)(A + (long)rowmap[row] * K + k0 + c4 * 4);
            As[c4 * 4 + 0][row] = v.x;
            As[c4 * 4 + 1][row] = v.y;
            As[c4 * 4 + 2][row] = v.z;
            As[c4 * 4 + 3][row] = v.w;
        }
        #pragma unroll
        for (int it = 0; it < 2; it++) {
            int f = tid + it * 256;
            int n = f >> 2, c4 = f & 3;
            float4 v = *(const float4*)(W + (long)(blockCol * 128 + n) * K + k0 + c4 * 4);
            Bs[c4 * 4 + 0][n] = v.x;
            Bs[c4 * 4 + 1][n] = v.y;
            Bs[c4 * 4 + 2][n] = v.z;
            Bs[c4 * 4 + 3][n] = v.w;
        }
        __syncthreads();
        #pragma unroll
        for (int k = 0; k < 16; k++) {
            float a[8], b[8];
            *(float4*)(a)     = *(const float4*)&As[k][ty * 8];
            *(float4*)(a + 4) = *(const float4*)&As[k][ty * 8 + 4];
            *(float4*)(b)     = *(const float4*)&Bs[k][tx * 8];
            *(float4*)(b + 4) = *(const float4*)&Bs[k][tx * 8 + 4];
            #pragma unroll
            for (int i = 0; i < 8; i++)
                #pragma unroll
                for (int j = 0; j < 8; j++) acc[i][j] = fmaf(a[i], b[j], acc[i][j]);
        }
        __syncthreads();
    }

    float bv[8];
    #pragma unroll
    for (int j = 0; j < 8; j++) bv[j] = bias[blockCol * 128 + tx * 8 + j];

    #pragma unroll
    for (int i = 0; i < 8; i++) {
        long r = blockRow * 128 + ty * 8 + i;
        float* op = out + r * (long)ldout + blockCol * 128 + tx * 8;
        #pragma unroll
        for (int j = 0; j < 8; j++) {
            float v = acc[i][j] + bv[j];
            if (EPI == 1) {
                v = 0.5f * v * (1.0f + erff(v * 0.70710678118654752f));
            } else if (EPI == 2) {
                v += resid[r * (long)CDIM + blockCol * 128 + tx * 8 + j];
            }
            op[j] = v;
        }
    }
}

// ---------------- window attention: one block per (window, head) ----------------
__global__ void __launch_bounds__(256)
attn_kernel(const float* __restrict__ qkv, const float* __restrict__ rpb,
            float* __restrict__ outw) {
    const int widx = blockIdx.x;
    const int head = blockIdx.y;
    __shared__ float Qs[49][33], Ks[49][33], Vs[49][33];
    __shared__ float S[49][50];
    __shared__ float rpbs[169];
    __shared__ int reg[49];
    const int tid = threadIdx.x;
    const float scale = 0.17677669529663687f;  // 32^-0.5

    const long base = (long)widx * 49 * 384 + head * 32;
    for (int p = tid; p < 49 * 32; p += 256) {
        int n = p >> 5, d = p & 31;
        Qs[n][d] = qkv[base + n * 384 + d] * scale;
        Ks[n][d] = qkv[base + n * 384 + 128 + d];
        Vs[n][d] = qkv[base + n * 384 + 256 + d];
    }
    if (tid < 169) rpbs[tid] = rpb[tid * 4 + head];
    if (tid < 49) {
        int wi = widx & 63;
        int wh = wi >> 3, ww = wi & 7;
        int i = tid / 7, j = tid - i * 7;
        int gr = wh * 7 + i, gc = ww * 7 + j;
        int rr = gr < 49 ? 0 : (gr < 53 ? 1 : 2);
        int rc = gc < 49 ? 0 : (gc < 53 ? 1 : 2);
        reg[tid] = rr * 3 + rc;
    }
    __syncthreads();

    for (int p = tid; p < 49 * 49; p += 256) {
        int n = p / 49, m = p - n * 49;
        float acc = 0.0f;
        #pragma unroll
        for (int k = 0; k < 32; k++) acc = fmaf(Qs[n][k], Ks[m][k], acc);
        int i1 = n / 7, j1 = n - i1 * 7;
        int i2 = m / 7, j2 = m - i2 * 7;
        acc += rpbs[(i1 - i2 + 6) * 13 + (j1 - j2 + 6)];
        if (reg[n] != reg[m]) acc -= 100.0f;
        S[n][m] = acc;
    }
    __syncthreads();

    // softmax, one warp per row
    const int warp = tid >> 5, lane = tid & 31;
    for (int n = warp; n < 49; n += 8) {
        float v0 = S[n][lane];
        float v1 = (lane + 32 < 49) ? S[n][lane + 32] : -1e30f;
        float mx = fmaxf(v0, v1);
        #pragma unroll
        for (int o = 16; o; o >>= 1) mx = fmaxf(mx, __shfl_xor_sync(0xFFFFFFFFu, mx, o));
        float e0 = __expf(v0 - mx);
        float e1 = (lane + 32 < 49) ? __expf(v1 - mx) : 0.0f;
        float sm = e0 + e1;
        #pragma unroll
        for (int o = 16; o; o >>= 1) sm += __shfl_xor_sync(0xFFFFFFFFu, sm, o);
        float inv = __frcp_rn(sm);
        S[n][lane] = e0 * inv;
        if (lane + 32 < 49) S[n][lane + 32] = e1 * inv;
    }
    __syncthreads();

    for (int p = tid; p < 49 * 32; p += 256) {
        int n = p >> 5, d = p & 31;
        float acc = 0.0f;
        #pragma unroll
        for (int m = 0; m < 49; m++) acc = fmaf(S[n][m], Vs[m][d], acc);
        outw[((long)widx * 49 + n) * CDIM + head * 32 + d] = acc;
    }
}

// ---------------- launch ----------------
extern "C" void kernel_launch(void* const* d_in, const int* in_sizes, int n_in,
                              void* d_out, int out_size) {
    const float* x      = (const float*)d_in[0];
    const float* n1g    = (const float*)d_in[1];
    const float* n1b    = (const float*)d_in[2];
    const float* qkv_w  = (const float*)d_in[3];
    const float* qkv_b  = (const float*)d_in[4];
    const float* proj_w = (const float*)d_in[5];
    const float* proj_b = (const float*)d_in[6];
    const float* rpb    = (const float*)d_in[7];
    const float* n2g    = (const float*)d_in[8];
    const float* n2b    = (const float*)d_in[9];
    const float* fc1_w  = (const float*)d_in[10];
    const float* fc1_b  = (const float*)d_in[11];
    const float* fc2_w  = (const float*)d_in[12];
    const float* fc2_b  = (const float*)d_in[13];
    float* out = (float*)d_out;

    float *xw, *qkvb, *attnb, *x1, *xn2, *hb;
    cudaGetSymbolAddress((void**)&xw,   g_xw);
    cudaGetSymbolAddress((void**)&qkvb, g_qkv);
    cudaGetSymbolAddress((void**)&attnb,g_attn);
    cudaGetSymbolAddress((void**)&x1,   g_x1);
    cudaGetSymbolAddress((void**)&xn2,  g_xn2);
    cudaGetSymbolAddress((void**)&hb,   g_h);

    // 1. LN1 + shift + window partition
    ln_kernel<1><<<MROWS / 8, 256>>>(x, n1g, n1b, xw);
    // 2. QKV GEMM  [M,128] @ [384,128]^T
    gemm_kernel<0, 0><<<dim3(MROWS / 128, 3), 256>>>(xw, qkv_w, qkv_b, nullptr, qkvb, 128, 384);
    // 3. window attention
    attn_kernel<<<dim3(NWB, NHEAD), 256>>>(qkvb, rpb, attnb);
    // 4. proj GEMM + window reverse + unshift + residual
    gemm_kernel<1, 2><<<dim3(MROWS / 128, 1), 256>>>(attnb, proj_w, proj_b, x, x1, 128, 128);
    // 5. LN2
    ln_kernel<0><<<MROWS / 8, 256>>>(x1, n2g, n2b, xn2);
    // 6. fc1 GEMM + GELU
    gemm_kernel<0, 1><<<dim3(MROWS / 128, 4), 256>>>(xn2, fc1_w, fc1_b, nullptr, hb, 128, 512);
    // 7. fc2 GEMM + residual -> out
    gemm_kernel<0, 2><<<dim3(MROWS / 128, 1), 256>>>(hb, fc2_w, fc2_b, x1, out, 512, 128);
}

// round 2
// speedup vs baseline: 2.6124x; 2.6124x over previous
#include <cuda_runtime.h>
#include <cuda_bf16.h>
#include <stdint.h>
#include <math.h>

// ---------------- problem constants ----------------
#define BATCH 64
#define HDIM 56
#define WDIM 56
#define CDIM 128
#define NHEAD 4
#define WSZ 7
#define SHIFT 3
#define NTOK 49
#define NWIN 64
#define NWB (BATCH * NWIN)
#define MROWS (NWB * NTOK)   // 200704
#define HID 512

// ---------------- scratch ----------------
__device__ __align__(256) __nv_bfloat16 g_xw[(size_t)MROWS * CDIM];
__device__ __align__(256) float         g_qkv[(size_t)MROWS * 3 * CDIM];
__device__ __align__(256) __nv_bfloat16 g_attn[(size_t)MROWS * CDIM];
__device__ __align__(256) float         g_x1[(size_t)MROWS * CDIM];
__device__ __align__(256) __nv_bfloat16 g_xn2[(size_t)MROWS * CDIM];
__device__ __align__(256) __nv_bfloat16 g_h[(size_t)MROWS * HID];
__device__ __align__(256) __nv_bfloat16 g_wq[3 * CDIM * CDIM];
__device__ __align__(256) __nv_bfloat16 g_wp[CDIM * CDIM];
__device__ __align__(256) __nv_bfloat16 g_w1[HID * CDIM];
__device__ __align__(256) __nv_bfloat16 g_w2[CDIM * HID];

// ---------------- fp32 -> bf16 conversion (weights) ----------------
__global__ void f2bf_kernel(const float* __restrict__ in, __nv_bfloat16* __restrict__ out, int n4) {
    int i = blockIdx.x * 256 + threadIdx.x;
    if (i < n4) {
        float4 v = ((const float4*)in)[i];
        __nv_bfloat162* o = ((__nv_bfloat162*)out) + i * 2;
        o[0] = __floats2bfloat162_rn(v.x, v.y);
        o[1] = __floats2bfloat162_rn(v.z, v.w);
    }
}

// ---------------- LayerNorm -> bf16 (optional shift+window gather) ----------------
template <int GATHER>
__global__ void ln_kernel(const float* __restrict__ x, const float* __restrict__ gamma,
                          const float* __restrict__ beta, __nv_bfloat16* __restrict__ out) {
    int token = blockIdx.x * 8 + (threadIdx.x >> 5);
    int lane = threadIdx.x & 31;
    long srow;
    if (GATHER) {
        int widx = token / NTOK, n = token % NTOK;
        int b = widx >> 6, wi = widx & 63;
        int wh = wi >> 3, ww = wi & 7;
        int i = n / 7, j = n - i * 7;
        int sh = wh * 7 + i + SHIFT; if (sh >= HDIM) sh -= HDIM;
        int sw = ww * 7 + j + SHIFT; if (sw >= WDIM) sw -= WDIM;
        srow = (long)b * (HDIM * WDIM) + sh * WDIM + sw;
    } else {
        srow = token;
    }
    float4 v = ((const float4*)(x + srow * (long)CDIM))[lane];
    float s = v.x + v.y + v.z + v.w;
    float sq = v.x * v.x + v.y * v.y + v.z * v.z + v.w * v.w;
    #pragma unroll
    for (int o = 16; o; o >>= 1) {
        s  += __shfl_xor_sync(0xFFFFFFFFu, s, o);
        sq += __shfl_xor_sync(0xFFFFFFFFu, sq, o);
    }
    float mu = s * (1.0f / 128.0f);
    float var = sq * (1.0f / 128.0f) - mu * mu;
    float inv = rsqrtf(var + 1e-5f);
    float4 g = ((const float4*)gamma)[lane];
    float4 b4 = ((const float4*)beta)[lane];
    float r0 = (v.x - mu) * inv * g.x + b4.x;
    float r1 = (v.y - mu) * inv * g.y + b4.y;
    float r2 = (v.z - mu) * inv * g.z + b4.z;
    float r3 = (v.w - mu) * inv * g.w + b4.w;
    __nv_bfloat162* op = ((__nv_bfloat162*)(out + (long)token * CDIM)) + lane * 2;
    op[0] = __floats2bfloat162_rn(r0, r1);
    op[1] = __floats2bfloat162_rn(r2, r3);
}

// ---------------- tensor-core helpers ----------------
__device__ __forceinline__ void ldsm4(uint32_t& r0, uint32_t& r1, uint32_t& r2, uint32_t& r3,
                                      uint32_t addr) {
    asm volatile("ldmatrix.sync.aligned.m8n8.x4.shared.b16 {%0,%1,%2,%3}, [%4];"
                 : "=r"(r0), "=r"(r1), "=r"(r2), "=r"(r3) : "r"(addr));
}
__device__ __forceinline__ void mma16816(float* c, const uint32_t* a, uint32_t b0, uint32_t b1) {
    asm volatile("mma.sync.aligned.m16n8k16.row.col.f32.bf16.bf16.f32 "
                 "{%0,%1,%2,%3}, {%4,%5,%6,%7}, {%8,%9}, {%0,%1,%2,%3};"
                 : "+f"(c[0]), "+f"(c[1]), "+f"(c[2]), "+f"(c[3])
                 : "r"(a[0]), "r"(a[1]), "r"(a[2]), "r"(a[3]), "r"(b0), "r"(b1));
}

// ---------------- bf16 tensor-core GEMM ----------------
// out[M,ldout] = A[rowmap(M),K](bf16) @ W[N,K](bf16)^T + bias, + epilogue
// BM=128, BN=128, BK=64. 256 threads = 8 warps (4 in M x 2 in N), warp tile 32x64.
// EPI: 0 = f32 out; 1 = exact GELU -> bf16 out; 2 = +resid (f32, ld=128) -> f32 out.
// Smem row stride 144B (9x16B chunks) -> ldmatrix conflict-free: (9r+c) mod 8 distinct.
template <int GATHER, int EPI>
__global__ void __launch_bounds__(256, 2)
bgemm(const __nv_bfloat16* __restrict__ A, const __nv_bfloat16* __restrict__ W,
      const float* __restrict__ bias, const float* __restrict__ resid,
      void* __restrict__ outp, int K, int ldout) {
    __shared__ __align__(16) unsigned char sA[128 * 144];
    __shared__ __align__(16) unsigned char sB[128 * 144];
    __shared__ int rowmap[128];
    const int tid = threadIdx.x;
    const int bR = blockIdx.x, bC = blockIdx.y;

    if (tid < 128) {
        int r = bR * 128 + tid;
        if (GATHER) {
            int b = r / (HDIM * WDIM);
            int l = r - b * (HDIM * WDIM);
            int h = l / WDIM, w = l - h * WDIM;
            int sh = h - SHIFT; if (sh < 0) sh += HDIM;
            int sw = w - SHIFT; if (sw < 0) sw += WDIM;
            int wh = sh / 7, i = sh - wh * 7;
            int ww = sw / 7, j = sw - ww * 7;
            rowmap[tid] = ((b * 64 + wh * 8 + ww) * 49 + i * 7 + j);
        } else {
            rowmap[tid] = r;
        }
    }
    __syncthreads();

    const int warp = tid >> 5, lane = tid & 31;
    const int wm = warp & 3, wn = warp >> 2;
    float acc[2][8][4];
    #pragma unroll
    for (int i = 0; i < 2; i++)
        #pragma unroll
        for (int j = 0; j < 8; j++)
            #pragma unroll
            for (int q = 0; q < 4; q++) acc[i][j][q] = 0.0f;

    for (int k0 = 0; k0 < K; k0 += 64) {
        #pragma unroll
        for (int it = 0; it < 4; it++) {
            int c = tid + it * 256;
            int row = c >> 3, pos = c & 7;
            uint4 va = *(const uint4*)(A + (size_t)rowmap[row] * K + k0 + pos * 8);
            *(uint4*)(sA + row * 144 + pos * 16) = va;
            uint4 vb = *(const uint4*)(W + (size_t)(bC * 128 + row) * K + k0 + pos * 8);
            *(uint4*)(sB + row * 144 + pos * 16) = vb;
        }
        __syncthreads();
        #pragma unroll
        for (int ks = 0; ks < 4; ks++) {
            const int kc = ks * 2;
            const int mat = lane >> 3, l7 = lane & 7;
            uint32_t a[2][4];
            #pragma unroll
            for (int tm = 0; tm < 2; tm++) {
                int r = wm * 32 + tm * 16 + (mat & 1) * 8 + l7;
                int c = kc + (mat >> 1);
                ldsm4(a[tm][0], a[tm][1], a[tm][2], a[tm][3],
                      (uint32_t)__cvta_generic_to_shared(sA + r * 144 + c * 16));
            }
            uint32_t b[4][4];
            #pragma unroll
            for (int tn2 = 0; tn2 < 4; tn2++) {
                int n = wn * 64 + tn2 * 16 + (mat >> 1) * 8 + l7;
                int c = kc + (mat & 1);
                ldsm4(b[tn2][0], b[tn2][1], b[tn2][2], b[tn2][3],
                      (uint32_t)__cvta_generic_to_shared(sB + n * 144 + c * 16));
            }
            #pragma unroll
            for (int tm = 0; tm < 2; tm++)
                #pragma unroll
                for (int tn = 0; tn < 8; tn++)
                    mma16816(acc[tm][tn], a[tm], b[tn >> 1][(tn & 1) * 2], b[tn >> 1][(tn & 1) * 2 + 1]);
        }
        __syncthreads();
    }

    // epilogue. acc layout: c0,c1 at (gr, gc..gc+1); c2,c3 at (gr+8, gc..gc+1)
    const int gr = lane >> 2, gc = (lane & 3) * 2;
    #pragma unroll
    for (int tm = 0; tm < 2; tm++) {
        #pragma unroll
        for (int tn = 0; tn < 8; tn++) {
            int col = bC * 128 + wn * 64 + tn * 8 + gc;
            float bs0 = bias[col], bs1 = bias[col + 1];
            int row0 = bR * 128 + wm * 32 + tm * 16 + gr;
            float v0 = acc[tm][tn][0] + bs0, v1 = acc[tm][tn][1] + bs1;
            float v2 = acc[tm][tn][2] + bs0, v3 = acc[tm][tn][3] + bs1;
            if (EPI == 0) {
                float* o = (float*)outp;
                *(float2*)(o + (size_t)row0 * ldout + col) = make_float2(v0, v1);
                *(float2*)(o + (size_t)(row0 + 8) * ldout + col) = make_float2(v2, v3);
            } else if (EPI == 1) {
                const float is2 = 0.70710678118654752f;
                v0 = 0.5f * v0 * (1.0f + erff(v0 * is2));
                v1 = 0.5f * v1 * (1.0f + erff(v1 * is2));
                v2 = 0.5f * v2 * (1.0f + erff(v2 * is2));
                v3 = 0.5f * v3 * (1.0f + erff(v3 * is2));
                __nv_bfloat16* o = (__nv_bfloat16*)outp;
                *(__nv_bfloat162*)(o + (size_t)row0 * ldout + col) = __floats2bfloat162_rn(v0, v1);
                *(__nv_bfloat162*)(o + (size_t)(row0 + 8) * ldout + col) = __floats2bfloat162_rn(v2, v3);
            } else {
                float* o = (float*)outp;
                float2 r0 = *(const float2*)(resid + (size_t)row0 * CDIM + col);
                float2 r1 = *(const float2*)(resid + (size_t)(row0 + 8) * CDIM + col);
                *(float2*)(o + (size_t)row0 * ldout + col) = make_float2(v0 + r0.x, v1 + r0.y);
                *(float2*)(o + (size_t)(row0 + 8) * ldout + col) = make_float2(v2 + r1.x, v3 + r1.y);
            }
        }
    }
}

// ---------------- window attention (fp32, one block per window x head) ----------------
__global__ void __launch_bounds__(256)
attn_kernel(const float* __restrict__ qkv, const float* __restrict__ rpb,
            __nv_bfloat16* __restrict__ outw) {
    const int widx = blockIdx.x;
    const int head = blockIdx.y;
    __shared__ float Qs[49][33], Ks[49][33], Vs[49][33];
    __shared__ float S[49][50];
    __shared__ float rpbs[169];
    __shared__ int reg[49];
    const int tid = threadIdx.x;
    const float scale = 0.17677669529663687f;

    const long base = (long)widx * 49 * 384 + head * 32;
    for (int p = tid; p < 49 * 32; p += 256) {
        int n = p >> 5, d = p & 31;
        Qs[n][d] = qkv[base + n * 384 + d] * scale;
        Ks[n][d] = qkv[base + n * 384 + 128 + d];
        Vs[n][d] = qkv[base + n * 384 + 256 + d];
    }
    if (tid < 169) rpbs[tid] = rpb[tid * 4 + head];
    if (tid < 49) {
        int wi = widx & 63;
        int wh = wi >> 3, ww = wi & 7;
        int i = tid / 7, j = tid - i * 7;
        int gr = wh * 7 + i, gc = ww * 7 + j;
        int rr = gr < 49 ? 0 : (gr < 53 ? 1 : 2);
        int rc = gc < 49 ? 0 : (gc < 53 ? 1 : 2);
        reg[tid] = rr * 3 + rc;
    }
    __syncthreads();

    for (int p = tid; p < 49 * 49; p += 256) {
        int n = p / 49, m = p - n * 49;
        float acc = 0.0f;
        #pragma unroll
        for (int k = 0; k < 32; k++) acc = fmaf(Qs[n][k], Ks[m][k], acc);
        int i1 = n / 7, j1 = n - i1 * 7;
        int i2 = m / 7, j2 = m - i2 * 7;
        acc += rpbs[(i1 - i2 + 6) * 13 + (j1 - j2 + 6)];
        if (reg[n] != reg[m]) acc -= 100.0f;
        S[n][m] = acc;
    }
    __syncthreads();

    const int warp = tid >> 5, lane = tid & 31;
    for (int n = warp; n < 49; n += 8) {
        float v0 = S[n][lane];
        float v1 = (lane + 32 < 49) ? S[n][lane + 32] : -1e30f;
        float mx = fmaxf(v0, v1);
        #pragma unroll
        for (int o = 16; o; o >>= 1) mx = fmaxf(mx, __shfl_xor_sync(0xFFFFFFFFu, mx, o));
        float e0 = __expf(v0 - mx);
        float e1 = (lane + 32 < 49) ? __expf(v1 - mx) : 0.0f;
        float sm = e0 + e1;
        #pragma unroll
        for (int o = 16; o; o >>= 1) sm += __shfl_xor_sync(0xFFFFFFFFu, sm, o);
        float inv = __frcp_rn(sm);
        S[n][lane] = e0 * inv;
        if (lane + 32 < 49) S[n][lane + 32] = e1 * inv;
    }
    __syncthreads();

    for (int p = tid; p < 49 * 32; p += 256) {
        int n = p >> 5, d = p & 31;
        float acc = 0.0f;
        #pragma unroll
        for (int m = 0; m < 49; m++) acc = fmaf(S[n][m], Vs[m][d], acc);
        outw[((long)widx * 49 + n) * CDIM + head * 32 + d] = __float2bfloat16(acc);
    }
}

// ---------------- launch ----------------
extern "C" void kernel_launch(void* const* d_in, const int* in_sizes, int n_in,
                              void* d_out, int out_size) {
    const float* x      = (const float*)d_in[0];
    const float* n1g    = (const float*)d_in[1];
    const float* n1b    = (const float*)d_in[2];
    const float* qkv_w  = (const float*)d_in[3];
    const float* qkv_b  = (const float*)d_in[4];
    const float* proj_w = (const float*)d_in[5];
    const float* proj_b = (const float*)d_in[6];
    const float* rpb    = (const float*)d_in[7];
    const float* n2g    = (const float*)d_in[8];
    const float* n2b    = (const float*)d_in[9];
    const float* fc1_w  = (const float*)d_in[10];
    const float* fc1_b  = (const float*)d_in[11];
    const float* fc2_w  = (const float*)d_in[12];
    const float* fc2_b  = (const float*)d_in[13];
    float* out = (float*)d_out;

    __nv_bfloat16 *xw, *attnb, *xn2, *hb, *wq, *wp, *w1, *w2;
    float *qkvb, *x1;
    cudaGetSymbolAddress((void**)&xw,   g_xw);
    cudaGetSymbolAddress((void**)&qkvb, g_qkv);
    cudaGetSymbolAddress((void**)&attnb,g_attn);
    cudaGetSymbolAddress((void**)&x1,   g_x1);
    cudaGetSymbolAddress((void**)&xn2,  g_xn2);
    cudaGetSymbolAddress((void**)&hb,   g_h);
    cudaGetSymbolAddress((void**)&wq,   g_wq);
    cudaGetSymbolAddress((void**)&wp,   g_wp);
    cudaGetSymbolAddress((void**)&w1,   g_w1);
    cudaGetSymbolAddress((void**)&w2,   g_w2);

    // weight conversions
    f2bf_kernel<<<(3 * CDIM * CDIM / 4 + 255) / 256, 256>>>(qkv_w, wq, 3 * CDIM * CDIM / 4);
    f2bf_kernel<<<(CDIM * CDIM / 4 + 255) / 256, 256>>>(proj_w, wp, CDIM * CDIM / 4);
    f2bf_kernel<<<(HID * CDIM / 4 + 255) / 256, 256>>>(fc1_w, w1, HID * CDIM / 4);
    f2bf_kernel<<<(CDIM * HID / 4 + 255) / 256, 256>>>(fc2_w, w2, CDIM * HID / 4);

    // 1. LN1 + shift + window partition -> bf16
    ln_kernel<1><<<MROWS / 8, 256>>>(x, n1g, n1b, xw);
    // 2. QKV GEMM (f32 out)
    bgemm<0, 0><<<dim3(MROWS / 128, 3), 256>>>(xw, wq, qkv_b, nullptr, qkvb, 128, 384);
    // 3. window attention -> bf16
    attn_kernel<<<dim3(NWB, NHEAD), 256>>>(qkvb, rpb, attnb);
    // 4. proj GEMM + window reverse/unshift gather + residual(x) -> f32 x1
    bgemm<1, 2><<<dim3(MROWS / 128, 1), 256>>>(attnb, wp, proj_b, x, x1, 128, 128);
    // 5. LN2 -> bf16
    ln_kernel<0><<<MROWS / 8, 256>>>(x1, n2g, n2b, xn2);
    // 6. fc1 GEMM + GELU -> bf16
    bgemm<0, 1><<<dim3(MROWS / 128, 4), 256>>>(xn2, w1, fc1_b, nullptr, hb, 128, 512);
    // 7. fc2 GEMM + residual(x1) -> out
    bgemm<0, 2><<<dim3(MROWS / 128, 1), 256>>>(hb, w2, fc2_b, x1, out, 512, 128);
}

// round 4
// speedup vs baseline: 5.2869x; 2.0238x over previous
#include <cuda_runtime.h>
#include <cuda_bf16.h>
#include <stdint.h>
#include <math.h>

// ---------------- problem constants ----------------
#define BATCH 64
#define HDIM 56
#define WDIM 56
#define CDIM 128
#define NHEAD 4
#define WSZ 7
#define SHIFT 3
#define NTOK 49
#define NWIN 64
#define NWB (BATCH * NWIN)
#define MROWS (NWB * NTOK)   // 200704
#define HID 512

// ---------------- scratch ----------------
__device__ __align__(256) __nv_bfloat16 g_xw[(size_t)MROWS * CDIM];
__device__ __align__(256) __nv_bfloat16 g_qkv[(size_t)MROWS * 3 * CDIM];
__device__ __align__(256) __nv_bfloat16 g_vlo[(size_t)MROWS * CDIM];
__device__ __align__(256) __nv_bfloat16 g_attn[(size_t)MROWS * CDIM];
__device__ __align__(256) float         g_x1[(size_t)MROWS * CDIM];
__device__ __align__(256) __nv_bfloat16 g_xn2[(size_t)MROWS * CDIM];
__device__ __align__(256) __nv_bfloat16 g_h[(size_t)MROWS * HID];
__device__ __align__(256) __nv_bfloat16 g_wq[3 * CDIM * CDIM];
__device__ __align__(256) __nv_bfloat16 g_wp[CDIM * CDIM];
__device__ __align__(256) __nv_bfloat16 g_w1[HID * CDIM];
__device__ __align__(256) __nv_bfloat16 g_w2[CDIM * HID];

// ---------------- fp32 -> bf16 (weights) ----------------
__global__ void f2bf_kernel(const float* __restrict__ in, __nv_bfloat16* __restrict__ out, int n4) {
    int i = blockIdx.x * 256 + threadIdx.x;
    if (i < n4) {
        float4 v = ((const float4*)in)[i];
        __nv_bfloat162* o = ((__nv_bfloat162*)out) + i * 2;
        o[0] = __floats2bfloat162_rn(v.x, v.y);
        o[1] = __floats2bfloat162_rn(v.z, v.w);
    }
}

// ---------------- LayerNorm -> bf16 (optional shift+window gather) ----------------
template <int GATHER>
__global__ void ln_kernel(const float* __restrict__ x, const float* __restrict__ gamma,
                          const float* __restrict__ beta, __nv_bfloat16* __restrict__ out) {
    int token = blockIdx.x * 8 + (threadIdx.x >> 5);
    int lane = threadIdx.x & 31;
    long srow;
    if (GATHER) {
        int widx = token / NTOK, n = token % NTOK;
        int b = widx >> 6, wi = widx & 63;
        int wh = wi >> 3, ww = wi & 7;
        int i = n / 7, j = n - i * 7;
        int sh = wh * 7 + i + SHIFT; if (sh >= HDIM) sh -= HDIM;
        int sw = ww * 7 + j + SHIFT; if (sw >= WDIM) sw -= WDIM;
        srow = (long)b * (HDIM * WDIM) + sh * WDIM + sw;
    } else {
        srow = token;
    }
    float4 v = ((const float4*)(x + srow * (long)CDIM))[lane];
    float s = v.x + v.y + v.z + v.w;
    float sq = v.x * v.x + v.y * v.y + v.z * v.z + v.w * v.w;
    #pragma unroll
    for (int o = 16; o; o >>= 1) {
        s  += __shfl_xor_sync(0xFFFFFFFFu, s, o);
        sq += __shfl_xor_sync(0xFFFFFFFFu, sq, o);
    }
    float mu = s * (1.0f / 128.0f);
    float var = sq * (1.0f / 128.0f) - mu * mu;
    float inv = rsqrtf(var + 1e-5f);
    float4 g = ((const float4*)gamma)[lane];
    float4 b4 = ((const float4*)beta)[lane];
    float r0 = (v.x - mu) * inv * g.x + b4.x;
    float r1 = (v.y - mu) * inv * g.y + b4.y;
    float r2 = (v.z - mu) * inv * g.z + b4.z;
    float r3 = (v.w - mu) * inv * g.w + b4.w;
    __nv_bfloat162* op = ((__nv_bfloat162*)(out + (long)token * CDIM)) + lane * 2;
    op[0] = __floats2bfloat162_rn(r0, r1);
    op[1] = __floats2bfloat162_rn(r2, r3);
}

// ---------------- tensor-core helpers ----------------
__device__ __forceinline__ void ldsm4(uint32_t& r0, uint32_t& r1, uint32_t& r2, uint32_t& r3,
                                      uint32_t addr) {
    asm volatile("ldmatrix.sync.aligned.m8n8.x4.shared.b16 {%0,%1,%2,%3}, [%4];"
                 : "=r"(r0), "=r"(r1), "=r"(r2), "=r"(r3) : "r"(addr));
}
__device__ __forceinline__ void ldsm4t(uint32_t& r0, uint32_t& r1, uint32_t& r2, uint32_t& r3,
                                       uint32_t addr) {
    asm volatile("ldmatrix.sync.aligned.m8n8.x4.trans.shared.b16 {%0,%1,%2,%3}, [%4];"
                 : "=r"(r0), "=r"(r1), "=r"(r2), "=r"(r3) : "r"(addr));
}
__device__ __forceinline__ void mma16816(float* c, const uint32_t* a, uint32_t b0, uint32_t b1) {
    asm volatile("mma.sync.aligned.m16n8k16.row.col.f32.bf16.bf16.f32 "
                 "{%0,%1,%2,%3}, {%4,%5,%6,%7}, {%8,%9}, {%0,%1,%2,%3};"
                 : "+f"(c[0]), "+f"(c[1]), "+f"(c[2]), "+f"(c[3])
                 : "r"(a[0]), "r"(a[1]), "r"(a[2]), "r"(a[3]), "r"(b0), "r"(b1));
}
__device__ __forceinline__ uint32_t pack_bf2(float a, float b) {
    __nv_bfloat162 t = __floats2bfloat162_rn(a, b);
    return *(uint32_t*)&t;
}
#define CP_ASYNC16(dst, src) asm volatile("cp.async.cg.shared.global [%0], [%1], 16;" :: "r"(dst), "l"(src))
#define CP_COMMIT() asm volatile("cp.async.commit_group;")

// ---------------- bf16 tensor-core GEMM, cp.async 2-stage ----------------
// EPI: 0 = bf16 out (bC==2 with lo!=null also writes bf16 residual plane);
//      1 = GELU->bf16; 2 = +resid -> f32; 3 = +resid -> f32 out1 AND fused LN2 -> bf16 out2
template <int GATHER, int EPI>
__global__ void __launch_bounds__(256, 2)
bgemm(const __nv_bfloat16* __restrict__ A, const __nv_bfloat16* __restrict__ W,
      const float* __restrict__ bias, const float* __restrict__ resid,
      void* __restrict__ out1, __nv_bfloat16* __restrict__ out2,
      const float* __restrict__ g2, const float* __restrict__ b2,
      __nv_bfloat16* __restrict__ lo, int K, int ldout) {
    extern __shared__ unsigned char smem[];
    int* rowmap = (int*)(smem + 73728);
    float2* red = (float2*)(smem + 74240);
    const int tid = threadIdx.x;
    const int bR = blockIdx.x, bC = blockIdx.y;

    if (tid < 128) {
        int r = bR * 128 + tid;
        if (GATHER) {
            int b = r / (HDIM * WDIM);
            int l = r - b * (HDIM * WDIM);
            int h = l / WDIM, w = l - h * WDIM;
            int sh = h - SHIFT; if (sh < 0) sh += HDIM;
            int sw = w - SHIFT; if (sw < 0) sw += WDIM;
            int wh = sh / 7, i = sh - wh * 7;
            int ww = sw / 7, j = sw - ww * 7;
            rowmap[tid] = ((b * 64 + wh * 8 + ww) * 49 + i * 7 + j);
        } else {
            rowmap[tid] = r;
        }
    }
    __syncthreads();

    const int warp = tid >> 5, lane = tid & 31;
    const int wm = warp & 3, wn = warp >> 2;
    const int ldrow = tid >> 3, ldpos = tid & 7;

    auto prefetch = [&](int s, int kt) {
        unsigned char* sa = smem + s * 36864;
        unsigned char* sb = sa + 18432;
        #pragma unroll
        for (int it = 0; it < 4; it++) {
            int row = ldrow + it * 32;
            uint32_t da = (uint32_t)__cvta_generic_to_shared(sa + row * 144 + ldpos * 16);
            CP_ASYNC16(da, A + (size_t)rowmap[row] * K + kt * 64 + ldpos * 8);
            uint32_t db = (uint32_t)__cvta_generic_to_shared(sb + row * 144 + ldpos * 16);
            CP_ASYNC16(db, W + (size_t)(bC * 128 + row) * K + kt * 64 + ldpos * 8);
        }
        CP_COMMIT();
    };

    float acc[2][8][4];
    #pragma unroll
    for (int i = 0; i < 2; i++)
        #pragma unroll
        for (int j = 0; j < 8; j++)
            #pragma unroll
            for (int q = 0; q < 4; q++) acc[i][j][q] = 0.0f;

    const int KT = K >> 6;
    prefetch(0, 0);
    for (int kt = 0; kt < KT; kt++) {
        if (kt + 1 < KT) prefetch((kt + 1) & 1, kt + 1);
        if (kt + 1 < KT) asm volatile("cp.async.wait_group 1;");
        else             asm volatile("cp.async.wait_group 0;");
        __syncthreads();
        unsigned char* sa = smem + (kt & 1) * 36864;
        unsigned char* sb = sa + 18432;
        #pragma unroll
        for (int ks = 0; ks < 4; ks++) {
            const int kc = ks * 2;
            const int mat = lane >> 3, l7 = lane & 7;
            uint32_t a[2][4];
            #pragma unroll
            for (int tm = 0; tm < 2; tm++) {
                int r = wm * 32 + tm * 16 + (mat & 1) * 8 + l7;
                int c = kc + (mat >> 1);
                ldsm4(a[tm][0], a[tm][1], a[tm][2], a[tm][3],
                      (uint32_t)__cvta_generic_to_shared(sa + r * 144 + c * 16));
            }
            uint32_t b[4][4];
            #pragma unroll
            for (int tn2 = 0; tn2 < 4; tn2++) {
                int n = wn * 64 + tn2 * 16 + (mat >> 1) * 8 + l7;
                int c = kc + (mat & 1);
                ldsm4(b[tn2][0], b[tn2][1], b[tn2][2], b[tn2][3],
                      (uint32_t)__cvta_generic_to_shared(sb + n * 144 + c * 16));
            }
            #pragma unroll
            for (int tm = 0; tm < 2; tm++)
                #pragma unroll
                for (int tn = 0; tn < 8; tn++)
                    mma16816(acc[tm][tn], a[tm], b[tn >> 1][(tn & 1) * 2], b[tn >> 1][(tn & 1) * 2 + 1]);
        }
        __syncthreads();
    }

    const int gr = lane >> 2, gc = (lane & 3) * 2;

    if (EPI == 3) {
        float psum[2][2], psq[2][2];
        #pragma unroll
        for (int tm = 0; tm < 2; tm++)
            #pragma unroll
            for (int sl = 0; sl < 2; sl++) { psum[tm][sl] = 0.0f; psq[tm][sl] = 0.0f; }
        #pragma unroll
        for (int tm = 0; tm < 2; tm++) {
            #pragma unroll
            for (int tn = 0; tn < 8; tn++) {
                int col = wn * 64 + tn * 8 + gc;
                float bs0 = bias[col], bs1 = bias[col + 1];
                int row0 = bR * 128 + wm * 32 + tm * 16 + gr;
                float2 r0 = *(const float2*)(resid + (size_t)row0 * CDIM + col);
                float2 r1 = *(const float2*)(resid + (size_t)(row0 + 8) * CDIM + col);
                float v0 = acc[tm][tn][0] + bs0 + r0.x;
                float v1 = acc[tm][tn][1] + bs1 + r0.y;
                float v2 = acc[tm][tn][2] + bs0 + r1.x;
                float v3 = acc[tm][tn][3] + bs1 + r1.y;
                acc[tm][tn][0] = v0; acc[tm][tn][1] = v1;
                acc[tm][tn][2] = v2; acc[tm][tn][3] = v3;
                psum[tm][0] += v0 + v1;  psq[tm][0] += v0 * v0 + v1 * v1;
                psum[tm][1] += v2 + v3;  psq[tm][1] += v2 * v2 + v3 * v3;
            }
        }
        #pragma unroll
        for (int tm = 0; tm < 2; tm++)
            #pragma unroll
            for (int sl = 0; sl < 2; sl++) {
                float s = psum[tm][sl], q = psq[tm][sl];
                s += __shfl_xor_sync(0xFFFFFFFFu, s, 1); q += __shfl_xor_sync(0xFFFFFFFFu, q, 1);
                s += __shfl_xor_sync(0xFFFFFFFFu, s, 2); q += __shfl_xor_sync(0xFFFFFFFFu, q, 2);
                if ((lane & 3) == 0) red[wn * 128 + wm * 32 + tm * 16 + sl * 8 + gr] = make_float2(s, q);
            }
        __syncthreads();
        float* o1 = (float*)out1;
        #pragma unroll
        for (int tm = 0; tm < 2; tm++) {
            #pragma unroll
            for (int sl = 0; sl < 2; sl++) {
                int lrow = wm * 32 + tm * 16 + sl * 8 + gr;
                float2 t0 = red[lrow], t1 = red[128 + lrow];
                float mu = (t0.x + t1.x) * (1.0f / 128.0f);
                float var = (t0.y + t1.y) * (1.0f / 128.0f) - mu * mu;
                float inv = rsqrtf(var + 1e-5f);
                size_t row = (size_t)bR * 128 + lrow;
                #pragma unroll
                for (int tn = 0; tn < 8; tn++) {
                    int col = wn * 64 + tn * 8 + gc;
                    float v0 = acc[tm][tn][sl * 2 + 0], v1 = acc[tm][tn][sl * 2 + 1];
                    *(float2*)(o1 + row * 128 + col) = make_float2(v0, v1);
                    float n0 = (v0 - mu) * inv * g2[col] + b2[col];
                    float n1 = (v1 - mu) * inv * g2[col + 1] + b2[col + 1];
                    *(__nv_bfloat162*)(out2 + row * 128 + col) = __floats2bfloat162_rn(n0, n1);
                }
            }
        }
        return;
    }

    #pragma unroll
    for (int tm = 0; tm < 2; tm++) {
        #pragma unroll
        for (int tn = 0; tn < 8; tn++) {
            int col = bC * 128 + wn * 64 + tn * 8 + gc;
            float bs0 = bias[col], bs1 = bias[col + 1];
            int row0 = bR * 128 + wm * 32 + tm * 16 + gr;
            float v0 = acc[tm][tn][0] + bs0, v1 = acc[tm][tn][1] + bs1;
            float v2 = acc[tm][tn][2] + bs0, v3 = acc[tm][tn][3] + bs1;
            if (EPI == 0) {
                __nv_bfloat16* o = (__nv_bfloat16*)out1;
                uint32_t u0 = pack_bf2(v0, v1), u1 = pack_bf2(v2, v3);
                *(uint32_t*)(o + (size_t)row0 * ldout + col) = u0;
                *(uint32_t*)(o + (size_t)(row0 + 8) * ldout + col) = u1;
                if (lo != nullptr && bC == 2) {
                    int lc = col - 256;
                    float h0 = __uint_as_float(u0 << 16), h1 = __uint_as_float(u0 & 0xFFFF0000u);
                    float h2 = __uint_as_float(u1 << 16), h3 = __uint_as_float(u1 & 0xFFFF0000u);
                    *(uint32_t*)(lo + (size_t)row0 * CDIM + lc) = pack_bf2(v0 - h0, v1 - h1);
                    *(uint32_t*)(lo + (size_t)(row0 + 8) * CDIM + lc) = pack_bf2(v2 - h2, v3 - h3);
                }
            } else if (EPI == 1) {
                const float is2 = 0.70710678118654752f;
                v0 = 0.5f * v0 * (1.0f + erff(v0 * is2));
                v1 = 0.5f * v1 * (1.0f + erff(v1 * is2));
                v2 = 0.5f * v2 * (1.0f + erff(v2 * is2));
                v3 = 0.5f * v3 * (1.0f + erff(v3 * is2));
                __nv_bfloat16* o = (__nv_bfloat16*)out1;
                *(__nv_bfloat162*)(o + (size_t)row0 * ldout + col) = __floats2bfloat162_rn(v0, v1);
                *(__nv_bfloat162*)(o + (size_t)(row0 + 8) * ldout + col) = __floats2bfloat162_rn(v2, v3);
            } else {
                float* o = (float*)out1;
                float2 r0 = *(const float2*)(resid + (size_t)row0 * CDIM + col);
                float2 r1 = *(const float2*)(resid + (size_t)(row0 + 8) * CDIM + col);
                *(float2*)(o + (size_t)row0 * ldout + col) = make_float2(v0 + r0.x, v1 + r0.y);
                *(float2*)(o + (size_t)(row0 + 8) * ldout + col) = make_float2(v2 + r1.x, v3 + r1.y);
            }
        }
    }
}

// ---------------- tensor-core window attention, split-precision P@V ----------------
// smem: QKVhi 4h x 3 x [64][80B] = 61440; Vlo 4h x [64][80B] @61440 (20480);
//       rpb @81920 (2704); regs @84624; i2t @84880; j2t @84944. total 85008.
__global__ void __launch_bounds__(256)
attn_kernel(const __nv_bfloat16* __restrict__ qkv, const __nv_bfloat16* __restrict__ vlo,
            const float* __restrict__ rpb, __nv_bfloat16* __restrict__ outw) {
    extern __shared__ unsigned char sm[];
    const int widx = blockIdx.x;
    const int tid = threadIdx.x;

    #pragma unroll
    for (int it = 0; it < 12; it++) {
        int idx = it * 256 + tid;
        int c4 = idx & 3, row = (idx >> 2) & 63, h = (idx >> 8) & 3, t = idx >> 10;
        uint4 v = make_uint4(0, 0, 0, 0);
        if (row < 49)
            v = *(const uint4*)(qkv + (size_t)widx * 18816 + row * 384 + t * 128 + h * 32 + c4 * 8);
        *(uint4*)(sm + h * 15360 + t * 5120 + row * 80 + c4 * 16) = v;
    }
    #pragma unroll
    for (int it = 0; it < 4; it++) {
        int idx = it * 256 + tid;
        int c4 = idx & 3, row = (idx >> 2) & 63, h = idx >> 8;
        uint4 v = make_uint4(0, 0, 0, 0);
        if (row < 49)
            v = *(const uint4*)(vlo + ((size_t)widx * 49 + row) * 128 + h * 32 + c4 * 8);
        *(uint4*)(sm + 61440 + h * 5120 + row * 80 + c4 * 16) = v;
    }
    float* rp = (float*)(sm + 81920);
    for (int p = tid; p < 676; p += 256) rp[p] = rpb[(p % 169) * 4 + (p / 169)];
    int* regs = (int*)(sm + 84624);
    signed char* i2t = (signed char*)(sm + 84880);
    signed char* j2t = (signed char*)(sm + 84944);
    if (tid < 64) { i2t[tid] = tid / 7; j2t[tid] = tid % 7; }
    if (tid < 49) {
        int wi = widx & 63;
        int wh = wi >> 3, ww = wi & 7;
        int i = tid / 7, j = tid - i * 7;
        int grr = wh * 7 + i, gcc = ww * 7 + j;
        int rr = grr < 49 ? 0 : (grr < 53 ? 1 : 2);
        int rc = gcc < 49 ? 0 : (gcc < 53 ? 1 : 2);
        regs[tid] = rr * 3 + rc;
    }
    __syncthreads();

    const int warp = tid >> 5, lane = tid & 31;
    const int h = warp >> 1, half = warp & 1;
    const int mat = lane >> 3, l7 = lane & 7, gr = lane >> 2, gc = (lane & 3) * 2;
    const unsigned char* Q = sm + h * 15360;
    const unsigned char* Kp = Q + 5120;
    const unsigned char* Vp = Q + 10240;
    const unsigned char* Vl = sm + 61440 + h * 5120;

    float sacc[2][8][4];
    #pragma unroll
    for (int i = 0; i < 2; i++)
        #pragma unroll
        for (int j = 0; j < 8; j++)
            #pragma unroll
            for (int q = 0; q < 4; q++) sacc[i][j][q] = 0.0f;

    #pragma unroll
    for (int kc = 0; kc < 2; kc++) {
        uint32_t a[2][4];
        #pragma unroll
        for (int tm = 0; tm < 2; tm++)
            ldsm4(a[tm][0], a[tm][1], a[tm][2], a[tm][3],
                  (uint32_t)__cvta_generic_to_shared(Q + (half * 32 + tm * 16 + (mat & 1) * 8 + l7) * 80 + kc * 32 + (mat >> 1) * 16));
        uint32_t b[4][4];
        #pragma unroll
        for (int tn2 = 0; tn2 < 4; tn2++)
            ldsm4(b[tn2][0], b[tn2][1], b[tn2][2], b[tn2][3],
                  (uint32_t)__cvta_generic_to_shared(Kp + (tn2 * 16 + (mat >> 1) * 8 + l7) * 80 + kc * 32 + (mat & 1) * 16));
        #pragma unroll
        for (int tm = 0; tm < 2; tm++)
            #pragma unroll
            for (int tn = 0; tn < 8; tn++)
                mma16816(sacc[tm][tn], a[tm], b[tn >> 1][(tn & 1) * 2], b[tn >> 1][(tn & 1) * 2 + 1]);
    }

    // softmax + split-precision P fragments (hi + lo)
    const float scale = 0.17677669529663687f;
    uint32_t pa[2][4][4], pl[2][4][4];
    #pragma unroll
    for (int tm = 0; tm < 2; tm++) {
        #pragma unroll
        for (int slot = 0; slot < 2; slot++) {
            int n = half * 32 + tm * 16 + gr + slot * 8;
            bool valid = n < 49;
            int i1 = 0, j1 = 0, regn = 0;
            if (valid) { i1 = i2t[n]; j1 = j2t[n]; regn = regs[n]; }
            float vv[16];
            float mx = -1e30f;
            #pragma unroll
            for (int tn = 0; tn < 8; tn++) {
                #pragma unroll
                for (int e = 0; e < 2; e++) {
                    int m = tn * 8 + gc + e;
                    float v = -1e30f;
                    if (valid && m < 49) {
                        v = sacc[tm][tn][slot * 2 + e] * scale
                          + rp[h * 169 + (i1 - i2t[m] + 6) * 13 + (j1 - j2t[m] + 6)];
                        if (regs[m] != regn) v -= 100.0f;
                    }
                    vv[tn * 2 + e] = v;
                    mx = fmaxf(mx, v);
                }
            }
            mx = fmaxf(mx, __shfl_xor_sync(0xFFFFFFFFu, mx, 1));
            mx = fmaxf(mx, __shfl_xor_sync(0xFFFFFFFFu, mx, 2));
            float sum = 0.0f;
            #pragma unroll
            for (int i = 0; i < 16; i++) { vv[i] = __expf(vv[i] - mx); sum += vv[i]; }
            sum += __shfl_xor_sync(0xFFFFFFFFu, sum, 1);
            sum += __shfl_xor_sync(0xFFFFFFFFu, sum, 2);
            float inv = valid ? __frcp_rn(sum) : 0.0f;
            #pragma unroll
            for (int tn = 0; tn < 8; tn++) {
                float p0 = vv[tn * 2] * inv, p1 = vv[tn * 2 + 1] * inv;
                uint32_t u = pack_bf2(p0, p1);
                pa[tm][tn >> 1][(tn & 1) * 2 + slot] = u;
                float h0 = __uint_as_float(u << 16), h1 = __uint_as_float(u & 0xFFFF0000u);
                pl[tm][tn >> 1][(tn & 1) * 2 + slot] = pack_bf2(p0 - h0, p1 - h1);
            }
        }
    }

    // O = P_hi@V_hi + P_lo@V_hi + P_hi@V_lo
    float oacc[2][4][4];
    #pragma unroll
    for (int i = 0; i < 2; i++)
        #pragma unroll
        for (int j = 0; j < 4; j++)
            #pragma unroll
            for (int q = 0; q < 4; q++) oacc[i][j][q] = 0.0f;

    #pragma unroll
    for (int kk = 0; kk < 4; kk++) {
        uint32_t bh[2][4], bl[2][4];
        #pragma unroll
        for (int dd = 0; dd < 2; dd++) {
            ldsm4t(bh[dd][0], bh[dd][1], bh[dd][2], bh[dd][3],
                   (uint32_t)__cvta_generic_to_shared(Vp + (kk * 16 + (mat & 1) * 8 + l7) * 80 + dd * 32 + (mat >> 1) * 16));
            ldsm4t(bl[dd][0], bl[dd][1], bl[dd][2], bl[dd][3],
                   (uint32_t)__cvta_generic_to_shared(Vl + (kk * 16 + (mat & 1) * 8 + l7) * 80 + dd * 32 + (mat >> 1) * 16));
        }
        #pragma unroll
        for (int tm = 0; tm < 2; tm++) {
            #pragma unroll
            for (int dd = 0; dd < 2; dd++) {
                mma16816(oacc[tm][dd * 2 + 0], pa[tm][kk], bh[dd][0], bh[dd][1]);
                mma16816(oacc[tm][dd * 2 + 0], pl[tm][kk], bh[dd][0], bh[dd][1]);
                mma16816(oacc[tm][dd * 2 + 0], pa[tm][kk], bl[dd][0], bl[dd][1]);
                mma16816(oacc[tm][dd * 2 + 1], pa[tm][kk], bh[dd][2], bh[dd][3]);
                mma16816(oacc[tm][dd * 2 + 1], pl[tm][kk], bh[dd][2], bh[dd][3]);
                mma16816(oacc[tm][dd * 2 + 1], pa[tm][kk], bl[dd][2], bl[dd][3]);
            }
        }
    }

    #pragma unroll
    for (int tm = 0; tm < 2; tm++) {
        int n0 = half * 32 + tm * 16 + gr;
        #pragma unroll
        for (int dt = 0; dt < 4; dt++) {
            int col = h * 32 + dt * 8 + gc;
            if (n0 < 49)
                *(__nv_bfloat162*)(outw + ((size_t)widx * 49 + n0) * 128 + col) =
                    __floats2bfloat162_rn(oacc[tm][dt][0], oacc[tm][dt][1]);
            if (n0 + 8 < 49)
                *(__nv_bfloat162*)(outw + ((size_t)widx * 49 + n0 + 8) * 128 + col) =
                    __floats2bfloat162_rn(oacc[tm][dt][2], oacc[tm][dt][3]);
        }
    }
}

// ---------------- launch ----------------
#define GEMM_SMEM 76288
#define ATTN_SMEM 85008

extern "C" void kernel_launch(void* const* d_in, const int* in_sizes, int n_in,
                              void* d_out, int out_size) {
    const float* x      = (const float*)d_in[0];
    const float* n1g    = (const float*)d_in[1];
    const float* n1b    = (const float*)d_in[2];
    const float* qkv_w  = (const float*)d_in[3];
    const float* qkv_b  = (const float*)d_in[4];
    const float* proj_w = (const float*)d_in[5];
    const float* proj_b = (const float*)d_in[6];
    const float* rpb    = (const float*)d_in[7];
    const float* n2g    = (const float*)d_in[8];
    const float* n2b    = (const float*)d_in[9];
    const float* fc1_w  = (const float*)d_in[10];
    const float* fc1_b  = (const float*)d_in[11];
    const float* fc2_w  = (const float*)d_in[12];
    const float* fc2_b  = (const float*)d_in[13];
    float* out = (float*)d_out;

    __nv_bfloat16 *xw, *qkvb, *vlo, *attnb, *xn2, *hb, *wq, *wp, *w1, *w2;
    float *x1;
    cudaGetSymbolAddress((void**)&xw,   g_xw);
    cudaGetSymbolAddress((void**)&qkvb, g_qkv);
    cudaGetSymbolAddress((void**)&vlo,  g_vlo);
    cudaGetSymbolAddress((void**)&attnb,g_attn);
    cudaGetSymbolAddress((void**)&x1,   g_x1);
    cudaGetSymbolAddress((void**)&xn2,  g_xn2);
    cudaGetSymbolAddress((void**)&hb,   g_h);
    cudaGetSymbolAddress((void**)&wq,   g_wq);
    cudaGetSymbolAddress((void**)&wp,   g_wp);
    cudaGetSymbolAddress((void**)&w1,   g_w1);
    cudaGetSymbolAddress((void**)&w2,   g_w2);

    cudaFuncSetAttribute((const void*)bgemm<0,0>, cudaFuncAttributeMaxDynamicSharedMemorySize, GEMM_SMEM);
    cudaFuncSetAttribute((const void*)bgemm<1,3>, cudaFuncAttributeMaxDynamicSharedMemorySize, GEMM_SMEM);
    cudaFuncSetAttribute((const void*)bgemm<0,1>, cudaFuncAttributeMaxDynamicSharedMemorySize, GEMM_SMEM);
    cudaFuncSetAttribute((const void*)bgemm<0,2>, cudaFuncAttributeMaxDynamicSharedMemorySize, GEMM_SMEM);
    cudaFuncSetAttribute((const void*)attn_kernel, cudaFuncAttributeMaxDynamicSharedMemorySize, ATTN_SMEM);

    f2bf_kernel<<<(3 * CDIM * CDIM / 4 + 255) / 256, 256>>>(qkv_w, wq, 3 * CDIM * CDIM / 4);
    f2bf_kernel<<<(CDIM * CDIM / 4 + 255) / 256, 256>>>(proj_w, wp, CDIM * CDIM / 4);
    f2bf_kernel<<<(HID * CDIM / 4 + 255) / 256, 256>>>(fc1_w, w1, HID * CDIM / 4);
    f2bf_kernel<<<(CDIM * HID / 4 + 255) / 256, 256>>>(fc2_w, w2, CDIM * HID / 4);

    // 1. LN1 + shift + window partition -> bf16
    ln_kernel<1><<<MROWS / 8, 256>>>(x, n1g, n1b, xw);
    // 2. QKV GEMM -> bf16 (+ V residual plane for split-precision PV)
    bgemm<0, 0><<<dim3(MROWS / 128, 3), 256, GEMM_SMEM>>>(xw, wq, qkv_b, nullptr, qkvb, nullptr, nullptr, nullptr, vlo, 128, 384);
    // 3. tensor-core window attention (split P/V) -> bf16
    attn_kernel<<<NWB, 256, ATTN_SMEM>>>(qkvb, vlo, rpb, attnb);
    // 4. proj GEMM + gather + residual(x) + fused LN2 -> x1 (f32), xn2 (bf16)
    bgemm<1, 3><<<dim3(MROWS / 128, 1), 256, GEMM_SMEM>>>(attnb, wp, proj_b, x, x1, xn2, n2g, n2b, nullptr, 128, 128);
    // 5. fc1 GEMM + GELU -> bf16
    bgemm<0, 1><<<dim3(MROWS / 128, 4), 256, GEMM_SMEM>>>(xn2, w1, fc1_b, nullptr, hb, nullptr, nullptr, nullptr, nullptr, 128, 512);
    // 6. fc2 GEMM + residual(x1) -> out
    bgemm<0, 2><<<dim3(MROWS / 128, 1), 256, GEMM_SMEM>>>(hb, w2, fc2_b, x1, out, nullptr, nullptr, nullptr, nullptr, 512, 128);
}

// round 6
// speedup vs baseline: 5.4232x; 1.0258x over previous
#include <cuda_runtime.h>
#include <cuda_bf16.h>
#include <stdint.h>
#include <math.h>

// ---------------- problem constants ----------------
#define BATCH 64
#define HDIM 56
#define WDIM 56
#define CDIM 128
#define NHEAD 4
#define WSZ 7
#define SHIFT 3
#define NTOK 49
#define NWIN 64
#define NWB (BATCH * NWIN)
#define MROWS (NWB * NTOK)   // 200704
#define HID 512

// ---------------- scratch ----------------
__device__ __align__(256) __nv_bfloat16 g_qkv[(size_t)MROWS * 3 * CDIM];
__device__ __align__(256) __nv_bfloat16 g_vlo[(size_t)MROWS * CDIM];
__device__ __align__(256) __nv_bfloat16 g_attn[(size_t)MROWS * CDIM];
__device__ __align__(256) float         g_x1[(size_t)MROWS * CDIM];
__device__ __align__(256) __nv_bfloat16 g_xn2[(size_t)MROWS * CDIM];
__device__ __align__(256) __nv_bfloat16 g_h[(size_t)MROWS * HID];
__device__ __align__(256) __nv_bfloat16 g_wq[3 * CDIM * CDIM];
__device__ __align__(256) __nv_bfloat16 g_wp[CDIM * CDIM];
__device__ __align__(256) __nv_bfloat16 g_w1[HID * CDIM];
__device__ __align__(256) __nv_bfloat16 g_w2[CDIM * HID];

// ---------------- tensor-core helpers ----------------
__device__ __forceinline__ void ldsm4(uint32_t& r0, uint32_t& r1, uint32_t& r2, uint32_t& r3,
                                      uint32_t addr) {
    asm volatile("ldmatrix.sync.aligned.m8n8.x4.shared.b16 {%0,%1,%2,%3}, [%4];"
                 : "=r"(r0), "=r"(r1), "=r"(r2), "=r"(r3) : "r"(addr));
}
__device__ __forceinline__ void ldsm4t(uint32_t& r0, uint32_t& r1, uint32_t& r2, uint32_t& r3,
                                       uint32_t addr) {
    asm volatile("ldmatrix.sync.aligned.m8n8.x4.trans.shared.b16 {%0,%1,%2,%3}, [%4];"
                 : "=r"(r0), "=r"(r1), "=r"(r2), "=r"(r3) : "r"(addr));
}
__device__ __forceinline__ void mma16816(float* c, const uint32_t* a, uint32_t b0, uint32_t b1) {
    asm volatile("mma.sync.aligned.m16n8k16.row.col.f32.bf16.bf16.f32 "
                 "{%0,%1,%2,%3}, {%4,%5,%6,%7}, {%8,%9}, {%0,%1,%2,%3};"
                 : "+f"(c[0]), "+f"(c[1]), "+f"(c[2]), "+f"(c[3])
                 : "r"(a[0]), "r"(a[1]), "r"(a[2]), "r"(a[3]), "r"(b0), "r"(b1));
}
__device__ __forceinline__ uint32_t pack_bf2(float a, float b) {
    __nv_bfloat162 t = __floats2bfloat162_rn(a, b);
    return *(uint32_t*)&t;
}
#define CP_ASYNC16(dst, src) asm volatile("cp.async.cg.shared.global [%0], [%1], 16;" :: "r"(dst), "l"(src))
#define CP_COMMIT() asm volatile("cp.async.commit_group;")

// 128x128x64 micro-step: sa/sb are 128-row x 64-col bf16 tiles (144B row stride)
__device__ __forceinline__ void mma_tile(const unsigned char* sa, const unsigned char* sb,
                                         int wm, int wn, int lane, float acc[2][8][4]) {
    const int mat = lane >> 3, l7 = lane & 7;
    #pragma unroll
    for (int ks = 0; ks < 4; ks++) {
        const int kc = ks * 2;
        uint32_t a[2][4];
        #pragma unroll
        for (int tm = 0; tm < 2; tm++) {
            int r = wm * 32 + tm * 16 + (mat & 1) * 8 + l7;
            int c = kc + (mat >> 1);
            ldsm4(a[tm][0], a[tm][1], a[tm][2], a[tm][3],
                  (uint32_t)__cvta_generic_to_shared(sa + r * 144 + c * 16));
        }
        uint32_t b[4][4];
        #pragma unroll
        for (int tn2 = 0; tn2 < 4; tn2++) {
            int n = wn * 64 + tn2 * 16 + (mat >> 1) * 8 + l7;
            int c = kc + (mat & 1);
            ldsm4(b[tn2][0], b[tn2][1], b[tn2][2], b[tn2][3],
                  (uint32_t)__cvta_generic_to_shared(sb + n * 144 + c * 16));
        }
        #pragma unroll
        for (int tm = 0; tm < 2; tm++)
            #pragma unroll
            for (int tn = 0; tn < 8; tn++)
                mma16816(acc[tm][tn], a[tm], b[tn >> 1][(tn & 1) * 2], b[tn >> 1][(tn & 1) * 2 + 1]);
    }
}

// ---------------- fp32 -> bf16 all four weights, one launch ----------------
__global__ void f2bf_all(const float* __restrict__ wq, const float* __restrict__ wp,
                         const float* __restrict__ w1, const float* __restrict__ w2,
                         __nv_bfloat16* oq, __nv_bfloat16* op,
                         __nv_bfloat16* o1, __nv_bfloat16* o2) {
    int i = blockIdx.x * 256 + threadIdx.x;   // float4 index; total 49152
    const float* src; __nv_bfloat16* dst; int off;
    if (i < 12288)      { src = wq; dst = oq; off = i; }
    else if (i < 16384) { src = wp; dst = op; off = i - 12288; }
    else if (i < 32768) { src = w1; dst = o1; off = i - 16384; }
    else                { src = w2; dst = o2; off = i - 32768; }
    float4 v = ((const float4*)src)[off];
    __nv_bfloat162* o = ((__nv_bfloat162*)dst) + off * 2;
    o[0] = __floats2bfloat162_rn(v.x, v.y);
    o[1] = __floats2bfloat162_rn(v.z, v.w);
}

// ---------------- fused LN1(+shift/window gather) + QKV GEMM ----------------
// smem: A0 @0, A1 @18432, Bbuf0 @36864, Bbuf1 @55296. total 73728.
__global__ void __launch_bounds__(256, 2)
qkv_fused(const float* __restrict__ x, const float* __restrict__ g1, const float* __restrict__ b1,
          const __nv_bfloat16* __restrict__ W, const float* __restrict__ bias,
          __nv_bfloat16* __restrict__ out, __nv_bfloat16* __restrict__ vlo) {
    extern __shared__ unsigned char smem[];
    const int tid = threadIdx.x;
    const int bR = blockIdx.x;
    const int warp = tid >> 5, lane = tid & 31;
    const int wm = warp & 3, wn = warp >> 2;
    const int ldrow = tid >> 3, ldpos = tid & 7;

    auto loadB = [&](int buf, int nt, int kt) {
        unsigned char* sb = smem + 36864 + buf * 18432;
        #pragma unroll
        for (int it = 0; it < 4; it++) {
            int row = ldrow + it * 32;
            uint32_t d = (uint32_t)__cvta_generic_to_shared(sb + row * 144 + ldpos * 16);
            CP_ASYNC16(d, W + (size_t)(nt * 128 + row) * 128 + kt * 64 + ldpos * 8);
        }
        CP_COMMIT();
    };

    loadB(0, 0, 0);
    loadB(1, 0, 1);

    // LN1 + gather into A tiles (warp w -> rows w*16..w*16+15)
    {
        float4 gv = ((const float4*)g1)[lane & 31];
        float4 bv = ((const float4*)b1)[lane & 31];
        unsigned char* At = smem + ((lane & 16) ? 18432 : 0);
        int off = (lane & 15) * 8;
        #pragma unroll 2
        for (int t = 0; t < 16; t++) {
            int row = warp * 16 + t;
            int r = bR * 128 + row;
            int widx = r / NTOK, n = r - widx * NTOK;
            int b = widx >> 6, wi = widx & 63;
            int wh = wi >> 3, ww = wi & 7;
            int i = n / 7, j = n - i * 7;
            int sh = wh * 7 + i + SHIFT; if (sh >= HDIM) sh -= HDIM;
            int sw = ww * 7 + j + SHIFT; if (sw >= WDIM) sw -= WDIM;
            long srow = (long)b * (HDIM * WDIM) + sh * WDIM + sw;
            float4 v = ((const float4*)(x + srow * (long)CDIM))[lane];
            float s = v.x + v.y + v.z + v.w;
            float sq = v.x * v.x + v.y * v.y + v.z * v.z + v.w * v.w;
            #pragma unroll
            for (int o = 16; o; o >>= 1) {
                s  += __shfl_xor_sync(0xFFFFFFFFu, s, o);
                sq += __shfl_xor_sync(0xFFFFFFFFu, sq, o);
            }
            float mu = s * (1.0f / 128.0f);
            float var = sq * (1.0f / 128.0f) - mu * mu;
            float inv = rsqrtf(var + 1e-5f);
            float r0 = (v.x - mu) * inv * gv.x + bv.x;
            float r1 = (v.y - mu) * inv * gv.y + bv.y;
            float r2 = (v.z - mu) * inv * gv.z + bv.z;
            float r3 = (v.w - mu) * inv * gv.w + bv.w;
            *(uint32_t*)(At + row * 144 + off)     = pack_bf2(r0, r1);
            *(uint32_t*)(At + row * 144 + off + 4) = pack_bf2(r2, r3);
        }
    }

    const int gr = lane >> 2, gc = (lane & 3) * 2;
    for (int nt = 0; nt < 3; nt++) {
        float acc[2][8][4];
        #pragma unroll
        for (int i = 0; i < 2; i++)
            #pragma unroll
            for (int j = 0; j < 8; j++)
                #pragma unroll
                for (int q = 0; q < 4; q++) acc[i][j][q] = 0.0f;
        #pragma unroll
        for (int kt = 0; kt < 2; kt++) {
            int idx = nt * 2 + kt;
            if (idx < 5) asm volatile("cp.async.wait_group 1;");
            else         asm volatile("cp.async.wait_group 0;");
            __syncthreads();
            mma_tile(smem + kt * 18432, smem + 36864 + (idx & 1) * 18432, wm, wn, lane, acc);
            __syncthreads();
            if (idx + 2 < 6) loadB(idx & 1, (idx + 2) >> 1, (idx + 2) & 1);
        }
        // epilogue: bias + bf16 store (nt==2 also writes V residual plane)
        #pragma unroll
        for (int tm = 0; tm < 2; tm++) {
            #pragma unroll
            for (int tn = 0; tn < 8; tn++) {
                int col = nt * 128 + wn * 64 + tn * 8 + gc;
                float bs0 = bias[col], bs1 = bias[col + 1];
                int row0 = bR * 128 + wm * 32 + tm * 16 + gr;
                float v0 = acc[tm][tn][0] + bs0, v1 = acc[tm][tn][1] + bs1;
                float v2 = acc[tm][tn][2] + bs0, v3 = acc[tm][tn][3] + bs1;
                uint32_t u0 = pack_bf2(v0, v1), u1 = pack_bf2(v2, v3);
                *(uint32_t*)(out + (size_t)row0 * 384 + col) = u0;
                *(uint32_t*)(out + (size_t)(row0 + 8) * 384 + col) = u1;
                if (nt == 2) {
                    int lc = col - 256;
                    float h0 = __uint_as_float(u0 << 16), h1 = __uint_as_float(u0 & 0xFFFF0000u);
                    float h2 = __uint_as_float(u1 << 16), h3 = __uint_as_float(u1 & 0xFFFF0000u);
                    *(uint32_t*)(vlo + (size_t)row0 * CDIM + lc) = pack_bf2(v0 - h0, v1 - h1);
                    *(uint32_t*)(vlo + (size_t)(row0 + 8) * CDIM + lc) = pack_bf2(v2 - h2, v3 - h3);
                }
            }
        }
    }
}

// ---------------- fused fc1 GEMM (all 4 column tiles, A resident) + GELU ----------------
__global__ void __launch_bounds__(256, 2)
fc1_fused(const __nv_bfloat16* __restrict__ A, const __nv_bfloat16* __restrict__ W,
          const float* __restrict__ bias, __nv_bfloat16* __restrict__ out) {
    extern __shared__ unsigned char smem[];
    const int tid = threadIdx.x;
    const int bR = blockIdx.x;
    const int warp = tid >> 5, lane = tid & 31;
    const int wm = warp & 3, wn = warp >> 2;
    const int ldrow = tid >> 3, ldpos = tid & 7;

    // A: both 64-K tiles, one commit group
    #pragma unroll
    for (int kt = 0; kt < 2; kt++)
        #pragma unroll
        for (int it = 0; it < 4; it++) {
            int row = ldrow + it * 32;
            uint32_t d = (uint32_t)__cvta_generic_to_shared(smem + kt * 18432 + row * 144 + ldpos * 16);
            CP_ASYNC16(d, A + (size_t)(bR * 128 + row) * 128 + kt * 64 + ldpos * 8);
        }
    CP_COMMIT();

    auto loadB = [&](int buf, int nt, int kt) {
        unsigned char* sb = smem + 36864 + buf * 18432;
        #pragma unroll
        for (int it = 0; it < 4; it++) {
            int row = ldrow + it * 32;
            uint32_t d = (uint32_t)__cvta_generic_to_shared(sb + row * 144 + ldpos * 16);
            CP_ASYNC16(d, W + (size_t)(nt * 128 + row) * 128 + kt * 64 + ldpos * 8);
        }
        CP_COMMIT();
    };
    loadB(0, 0, 0);
    loadB(1, 0, 1);

    const int gr = lane >> 2, gc = (lane & 3) * 2;
    for (int nt = 0; nt < 4; nt++) {
        float acc[2][8][4];
        #pragma unroll
        for (int i = 0; i < 2; i++)
            #pragma unroll
            for (int j = 0; j < 8; j++)
                #pragma unroll
                for (int q = 0; q < 4; q++) acc[i][j][q] = 0.0f;
        #pragma unroll
        for (int kt = 0; kt < 2; kt++) {
            int idx = nt * 2 + kt;
            if (idx < 7) asm volatile("cp.async.wait_group 1;");
            else         asm volatile("cp.async.wait_group 0;");
            __syncthreads();
            mma_tile(smem + kt * 18432, smem + 36864 + (idx & 1) * 18432, wm, wn, lane, acc);
            __syncthreads();
            if (idx + 2 < 8) loadB(idx & 1, (idx + 2) >> 1, (idx + 2) & 1);
        }
        const float is2 = 0.70710678118654752f;
        #pragma unroll
        for (int tm = 0; tm < 2; tm++) {
            #pragma unroll
            for (int tn = 0; tn < 8; tn++) {
                int col = nt * 128 + wn * 64 + tn * 8 + gc;
                float bs0 = bias[col], bs1 = bias[col + 1];
                int row0 = bR * 128 + wm * 32 + tm * 16 + gr;
                float v0 = acc[tm][tn][0] + bs0, v1 = acc[tm][tn][1] + bs1;
                float v2 = acc[tm][tn][2] + bs0, v3 = acc[tm][tn][3] + bs1;
                v0 = 0.5f * v0 * (1.0f + erff(v0 * is2));
                v1 = 0.5f * v1 * (1.0f + erff(v1 * is2));
                v2 = 0.5f * v2 * (1.0f + erff(v2 * is2));
                v3 = 0.5f * v3 * (1.0f + erff(v3 * is2));
                *(uint32_t*)(out + (size_t)row0 * 512 + col) = pack_bf2(v0, v1);
                *(uint32_t*)(out + (size_t)(row0 + 8) * 512 + col) = pack_bf2(v2, v3);
            }
        }
    }
}

// ---------------- bf16 GEMM, cp.async 2-stage (proj EPI=3, fc2 EPI=2) ----------------
template <int GATHER, int EPI>
__global__ void __launch_bounds__(256, 2)
bgemm(const __nv_bfloat16* __restrict__ A, const __nv_bfloat16* __restrict__ W,
      const float* __restrict__ bias, const float* __restrict__ resid,
      void* __restrict__ out1, __nv_bfloat16* __restrict__ out2,
      const float* __restrict__ g2, const float* __restrict__ b2, int K, int ldout) {
    extern __shared__ unsigned char smem[];
    int* rowmap = (int*)(smem + 73728);
    float2* red = (float2*)(smem + 74240);
    const int tid = threadIdx.x;
    const int bR = blockIdx.x, bC = blockIdx.y;

    if (tid < 128) {
        int r = bR * 128 + tid;
        if (GATHER) {
            int b = r / (HDIM * WDIM);
            int l = r - b * (HDIM * WDIM);
            int h = l / WDIM, w = l - h * WDIM;
            int sh = h - SHIFT; if (sh < 0) sh += HDIM;
            int sw = w - SHIFT; if (sw < 0) sw += WDIM;
            int wh = sh / 7, i = sh - wh * 7;
            int ww = sw / 7, j = sw - ww * 7;
            rowmap[tid] = ((b * 64 + wh * 8 + ww) * 49 + i * 7 + j);
        } else {
            rowmap[tid] = r;
        }
    }
    __syncthreads();

    const int warp = tid >> 5, lane = tid & 31;
    const int wm = warp & 3, wn = warp >> 2;
    const int ldrow = tid >> 3, ldpos = tid & 7;

    auto prefetch = [&](int s, int kt) {
        unsigned char* sa = smem + s * 36864;
        unsigned char* sb = sa + 18432;
        #pragma unroll
        for (int it = 0; it < 4; it++) {
            int row = ldrow + it * 32;
            uint32_t da = (uint32_t)__cvta_generic_to_shared(sa + row * 144 + ldpos * 16);
            CP_ASYNC16(da, A + (size_t)rowmap[row] * K + kt * 64 + ldpos * 8);
            uint32_t db = (uint32_t)__cvta_generic_to_shared(sb + row * 144 + ldpos * 16);
            CP_ASYNC16(db, W + (size_t)(bC * 128 + row) * K + kt * 64 + ldpos * 8);
        }
        CP_COMMIT();
    };

    float acc[2][8][4];
    #pragma unroll
    for (int i = 0; i < 2; i++)
        #pragma unroll
        for (int j = 0; j < 8; j++)
            #pragma unroll
            for (int q = 0; q < 4; q++) acc[i][j][q] = 0.0f;

    const int KT = K >> 6;
    prefetch(0, 0);
    for (int kt = 0; kt < KT; kt++) {
        if (kt + 1 < KT) prefetch((kt + 1) & 1, kt + 1);
        if (kt + 1 < KT) asm volatile("cp.async.wait_group 1;");
        else             asm volatile("cp.async.wait_group 0;");
        __syncthreads();
        unsigned char* sa = smem + (kt & 1) * 36864;
        mma_tile(sa, sa + 18432, wm, wn, lane, acc);
        __syncthreads();
    }

    const int gr = lane >> 2, gc = (lane & 3) * 2;

    if (EPI == 3) {
        float psum[2][2], psq[2][2];
        #pragma unroll
        for (int tm = 0; tm < 2; tm++)
            #pragma unroll
            for (int sl = 0; sl < 2; sl++) { psum[tm][sl] = 0.0f; psq[tm][sl] = 0.0f; }
        #pragma unroll
        for (int tm = 0; tm < 2; tm++) {
            #pragma unroll
            for (int tn = 0; tn < 8; tn++) {
                int col = wn * 64 + tn * 8 + gc;
                float bs0 = bias[col], bs1 = bias[col + 1];
                int row0 = bR * 128 + wm * 32 + tm * 16 + gr;
                float2 r0 = *(const float2*)(resid + (size_t)row0 * CDIM + col);
                float2 r1 = *(const float2*)(resid + (size_t)(row0 + 8) * CDIM + col);
                float v0 = acc[tm][tn][0] + bs0 + r0.x;
                float v1 = acc[tm][tn][1] + bs1 + r0.y;
                float v2 = acc[tm][tn][2] + bs0 + r1.x;
                float v3 = acc[tm][tn][3] + bs1 + r1.y;
                acc[tm][tn][0] = v0; acc[tm][tn][1] = v1;
                acc[tm][tn][2] = v2; acc[tm][tn][3] = v3;
                psum[tm][0] += v0 + v1;  psq[tm][0] += v0 * v0 + v1 * v1;
                psum[tm][1] += v2 + v3;  psq[tm][1] += v2 * v2 + v3 * v3;
            }
        }
        #pragma unroll
        for (int tm = 0; tm < 2; tm++)
            #pragma unroll
            for (int sl = 0; sl < 2; sl++) {
                float s = psum[tm][sl], q = psq[tm][sl];
                s += __shfl_xor_sync(0xFFFFFFFFu, s, 1); q += __shfl_xor_sync(0xFFFFFFFFu, q, 1);
                s += __shfl_xor_sync(0xFFFFFFFFu, s, 2); q += __shfl_xor_sync(0xFFFFFFFFu, q, 2);
                if ((lane & 3) == 0) red[wn * 128 + wm * 32 + tm * 16 + sl * 8 + gr] = make_float2(s, q);
            }
        __syncthreads();
        float* o1 = (float*)out1;
        #pragma unroll
        for (int tm = 0; tm < 2; tm++) {
            #pragma unroll
            for (int sl = 0; sl < 2; sl++) {
                int lrow = wm * 32 + tm * 16 + sl * 8 + gr;
                float2 t0 = red[lrow], t1 = red[128 + lrow];
                float mu = (t0.x + t1.x) * (1.0f / 128.0f);
                float var = (t0.y + t1.y) * (1.0f / 128.0f) - mu * mu;
                float inv = rsqrtf(var + 1e-5f);
                size_t row = (size_t)bR * 128 + lrow;
                #pragma unroll
                for (int tn = 0; tn < 8; tn++) {
                    int col = wn * 64 + tn * 8 + gc;
                    float v0 = acc[tm][tn][sl * 2 + 0], v1 = acc[tm][tn][sl * 2 + 1];
                    *(float2*)(o1 + row * 128 + col) = make_float2(v0, v1);
                    float n0 = (v0 - mu) * inv * g2[col] + b2[col];
                    float n1 = (v1 - mu) * inv * g2[col + 1] + b2[col + 1];
                    *(__nv_bfloat162*)(out2 + row * 128 + col) = __floats2bfloat162_rn(n0, n1);
                }
            }
        }
        return;
    }

    #pragma unroll
    for (int tm = 0; tm < 2; tm++) {
        #pragma unroll
        for (int tn = 0; tn < 8; tn++) {
            int col = bC * 128 + wn * 64 + tn * 8 + gc;
            float bs0 = bias[col], bs1 = bias[col + 1];
            int row0 = bR * 128 + wm * 32 + tm * 16 + gr;
            float v0 = acc[tm][tn][0] + bs0, v1 = acc[tm][tn][1] + bs1;
            float v2 = acc[tm][tn][2] + bs0, v3 = acc[tm][tn][3] + bs1;
            float* o = (float*)out1;
            float2 r0 = *(const float2*)(resid + (size_t)row0 * CDIM + col);
            float2 r1 = *(const float2*)(resid + (size_t)(row0 + 8) * CDIM + col);
            *(float2*)(o + (size_t)row0 * ldout + col) = make_float2(v0 + r0.x, v1 + r0.y);
            *(float2*)(o + (size_t)(row0 + 8) * ldout + col) = make_float2(v2 + r1.x, v3 + r1.y);
        }
    }
}

// ---------------- tensor-core window attention, split-precision P@V ----------------
__global__ void __launch_bounds__(256)
attn_kernel(const __nv_bfloat16* __restrict__ qkv, const __nv_bfloat16* __restrict__ vlo,
            const float* __restrict__ rpb, __nv_bfloat16* __restrict__ outw) {
    extern __shared__ unsigned char sm[];
    const int widx = blockIdx.x;
    const int tid = threadIdx.x;

    #pragma unroll
    for (int it = 0; it < 12; it++) {
        int idx = it * 256 + tid;
        int c4 = idx & 3, row = (idx >> 2) & 63, h = (idx >> 8) & 3, t = idx >> 10;
        uint4 v = make_uint4(0, 0, 0, 0);
        if (row < 49)
            v = *(const uint4*)(qkv + (size_t)widx * 18816 + row * 384 + t * 128 + h * 32 + c4 * 8);
        *(uint4*)(sm + h * 15360 + t * 5120 + row * 80 + c4 * 16) = v;
    }
    #pragma unroll
    for (int it = 0; it < 4; it++) {
        int idx = it * 256 + tid;
        int c4 = idx & 3, row = (idx >> 2) & 63, h = idx >> 8;
        uint4 v = make_uint4(0, 0, 0, 0);
        if (row < 49)
            v = *(const uint4*)(vlo + ((size_t)widx * 49 + row) * 128 + h * 32 + c4 * 8);
        *(uint4*)(sm + 61440 + h * 5120 + row * 80 + c4 * 16) = v;
    }
    float* rp = (float*)(sm + 81920);
    for (int p = tid; p < 676; p += 256) rp[p] = rpb[(p % 169) * 4 + (p / 169)];
    int* regs = (int*)(sm + 84624);
    signed char* i2t = (signed char*)(sm + 84880);
    signed char* j2t = (signed char*)(sm + 84944);
    if (tid < 64) { i2t[tid] = tid / 7; j2t[tid] = tid % 7; }
    if (tid < 49) {
        int wi = widx & 63;
        int wh = wi >> 3, ww = wi & 7;
        int i = tid / 7, j = tid - i * 7;
        int grr = wh * 7 + i, gcc = ww * 7 + j;
        int rr = grr < 49 ? 0 : (grr < 53 ? 1 : 2);
        int rc = gcc < 49 ? 0 : (gcc < 53 ? 1 : 2);
        regs[tid] = rr * 3 + rc;
    }
    __syncthreads();

    const int warp = tid >> 5, lane = tid & 31;
    const int h = warp >> 1, half = warp & 1;
    const int mat = lane >> 3, l7 = lane & 7, gr = lane >> 2, gc = (lane & 3) * 2;
    const unsigned char* Q = sm + h * 15360;
    const unsigned char* Kp = Q + 5120;
    const unsigned char* Vp = Q + 10240;
    const unsigned char* Vl = sm + 61440 + h * 5120;

    float sacc[2][8][4];
    #pragma unroll
    for (int i = 0; i < 2; i++)
        #pragma unroll
        for (int j = 0; j < 8; j++)
            #pragma unroll
            for (int q = 0; q < 4; q++) sacc[i][j][q] = 0.0f;

    #pragma unroll
    for (int kc = 0; kc < 2; kc++) {
        uint32_t a[2][4];
        #pragma unroll
        for (int tm = 0; tm < 2; tm++)
            ldsm4(a[tm][0], a[tm][1], a[tm][2], a[tm][3],
                  (uint32_t)__cvta_generic_to_shared(Q + (half * 32 + tm * 16 + (mat & 1) * 8 + l7) * 80 + kc * 32 + (mat >> 1) * 16));
        uint32_t b[4][4];
        #pragma unroll
        for (int tn2 = 0; tn2 < 4; tn2++)
            ldsm4(b[tn2][0], b[tn2][1], b[tn2][2], b[tn2][3],
                  (uint32_t)__cvta_generic_to_shared(Kp + (tn2 * 16 + (mat >> 1) * 8 + l7) * 80 + kc * 32 + (mat & 1) * 16));
        #pragma unroll
        for (int tm = 0; tm < 2; tm++)
            #pragma unroll
            for (int tn = 0; tn < 8; tn++)
                mma16816(sacc[tm][tn], a[tm], b[tn >> 1][(tn & 1) * 2], b[tn >> 1][(tn & 1) * 2 + 1]);
    }

    const float scale = 0.17677669529663687f;
    uint32_t pa[2][4][4], pl[2][4][4];
    #pragma unroll
    for (int tm = 0; tm < 2; tm++) {
        #pragma unroll
        for (int slot = 0; slot < 2; slot++) {
            int n = half * 32 + tm * 16 + gr + slot * 8;
            bool valid = n < 49;
            int i1 = 0, j1 = 0, regn = 0;
            if (valid) { i1 = i2t[n]; j1 = j2t[n]; regn = regs[n]; }
            float vv[16];
            float mx = -1e30f;
            #pragma unroll
            for (int tn = 0; tn < 8; tn++) {
                #pragma unroll
                for (int e = 0; e < 2; e++) {
                    int m = tn * 8 + gc + e;
                    float v = -1e30f;
                    if (valid && m < 49) {
                        v = sacc[tm][tn][slot * 2 + e] * scale
                          + rp[h * 169 + (i1 - i2t[m] + 6) * 13 + (j1 - j2t[m] + 6)];
                        if (regs[m] != regn) v -= 100.0f;
                    }
                    vv[tn * 2 + e] = v;
                    mx = fmaxf(mx, v);
                }
            }
            mx = fmaxf(mx, __shfl_xor_sync(0xFFFFFFFFu, mx, 1));
            mx = fmaxf(mx, __shfl_xor_sync(0xFFFFFFFFu, mx, 2));
            float sum = 0.0f;
            #pragma unroll
            for (int i = 0; i < 16; i++) { vv[i] = __expf(vv[i] - mx); sum += vv[i]; }
            sum += __shfl_xor_sync(0xFFFFFFFFu, sum, 1);
            sum += __shfl_xor_sync(0xFFFFFFFFu, sum, 2);
            float inv = valid ? __frcp_rn(sum) : 0.0f;
            #pragma unroll
            for (int tn = 0; tn < 8; tn++) {
                float p0 = vv[tn * 2] * inv, p1 = vv[tn * 2 + 1] * inv;
                uint32_t u = pack_bf2(p0, p1);
                pa[tm][tn >> 1][(tn & 1) * 2 + slot] = u;
                float h0 = __uint_as_float(u << 16), h1 = __uint_as_float(u & 0xFFFF0000u);
                pl[tm][tn >> 1][(tn & 1) * 2 + slot] = pack_bf2(p0 - h0, p1 - h1);
            }
        }
    }

    float oacc[2][4][4];
    #pragma unroll
    for (int i = 0; i < 2; i++)
        #pragma unroll
        for (int j = 0; j < 4; j++)
            #pragma unroll
            for (int q = 0; q < 4; q++) oacc[i][j][q] = 0.0f;

    #pragma unroll
    for (int kk = 0; kk < 4; kk++) {
        uint32_t bh[2][4], bl[2][4];
        #pragma unroll
        for (int dd = 0; dd < 2; dd++) {
            ldsm4t(bh[dd][0], bh[dd][1], bh[dd][2], bh[dd][3],
                   (uint32_t)__cvta_generic_to_shared(Vp + (kk * 16 + (mat & 1) * 8 + l7) * 80 + dd * 32 + (mat >> 1) * 16));
            ldsm4t(bl[dd][0], bl[dd][1], bl[dd][2], bl[dd][3],
                   (uint32_t)__cvta_generic_to_shared(Vl + (kk * 16 + (mat & 1) * 8 + l7) * 80 + dd * 32 + (mat >> 1) * 16));
        }
        #pragma unroll
        for (int tm = 0; tm < 2; tm++) {
            #pragma unroll
            for (int dd = 0; dd < 2; dd++) {
                mma16816(oacc[tm][dd * 2 + 0], pa[tm][kk], bh[dd][0], bh[dd][1]);
                mma16816(oacc[tm][dd * 2 + 0], pl[tm][kk], bh[dd][0], bh[dd][1]);
                mma16816(oacc[tm][dd * 2 + 0], pa[tm][kk], bl[dd][0], bl[dd][1]);
                mma16816(oacc[tm][dd * 2 + 1], pa[tm][kk], bh[dd][2], bh[dd][3]);
                mma16816(oacc[tm][dd * 2 + 1], pl[tm][kk], bh[dd][2], bh[dd][3]);
                mma16816(oacc[tm][dd * 2 + 1], pa[tm][kk], bl[dd][2], bl[dd][3]);
            }
        }
    }

    #pragma unroll
    for (int tm = 0; tm < 2; tm++) {
        int n0 = half * 32 + tm * 16 + gr;
        #pragma unroll
        for (int dt = 0; dt < 4; dt++) {
            int col = h * 32 + dt * 8 + gc;
            if (n0 < 49)
                *(__nv_bfloat162*)(outw + ((size_t)widx * 49 + n0) * 128 + col) =
                    __floats2bfloat162_rn(oacc[tm][dt][0], oacc[tm][dt][1]);
            if (n0 + 8 < 49)
                *(__nv_bfloat162*)(outw + ((size_t)widx * 49 + n0 + 8) * 128 + col) =
                    __floats2bfloat162_rn(oacc[tm][dt][2], oacc[tm][dt][3]);
        }
    }
}

// ---------------- launch ----------------
#define FUSED_SMEM 73728
#define GEMM_SMEM 76288
#define ATTN_SMEM 85008

extern "C" void kernel_launch(void* const* d_in, const int* in_sizes, int n_in,
                              void* d_out, int out_size) {
    const float* x      = (const float*)d_in[0];
    const float* n1g    = (const float*)d_in[1];
    const float* n1b    = (const float*)d_in[2];
    const float* qkv_w  = (const float*)d_in[3];
    const float* qkv_b  = (const float*)d_in[4];
    const float* proj_w = (const float*)d_in[5];
    const float* proj_b = (const float*)d_in[6];
    const float* rpb    = (const float*)d_in[7];
    const float* n2g    = (const float*)d_in[8];
    const float* n2b    = (const float*)d_in[9];
    const float* fc1_w  = (const float*)d_in[10];
    const float* fc1_b  = (const float*)d_in[11];
    const float* fc2_w  = (const float*)d_in[12];
    const float* fc2_b  = (const float*)d_in[13];
    float* out = (float*)d_out;

    __nv_bfloat16 *qkvb, *vlo, *attnb, *xn2, *hb, *wq, *wp, *w1, *w2;
    float *x1;
    cudaGetSymbolAddress((void**)&qkvb, g_qkv);
    cudaGetSymbolAddress((void**)&vlo,  g_vlo);
    cudaGetSymbolAddress((void**)&attnb,g_attn);
    cudaGetSymbolAddress((void**)&x1,   g_x1);
    cudaGetSymbolAddress((void**)&xn2,  g_xn2);
    cudaGetSymbolAddress((void**)&hb,   g_h);
    cudaGetSymbolAddress((void**)&wq,   g_wq);
    cudaGetSymbolAddress((void**)&wp,   g_wp);
    cudaGetSymbolAddress((void**)&w1,   g_w1);
    cudaGetSymbolAddress((void**)&w2,   g_w2);

    cudaFuncSetAttribute((const void*)qkv_fused, cudaFuncAttributeMaxDynamicSharedMemorySize, FUSED_SMEM);
    cudaFuncSetAttribute((const void*)fc1_fused, cudaFuncAttributeMaxDynamicSharedMemorySize, FUSED_SMEM);
    cudaFuncSetAttribute((const void*)bgemm<1,3>, cudaFuncAttributeMaxDynamicSharedMemorySize, GEMM_SMEM);
    cudaFuncSetAttribute((const void*)bgemm<0,2>, cudaFuncAttributeMaxDynamicSharedMemorySize, GEMM_SMEM);
    cudaFuncSetAttribute((const void*)attn_kernel, cudaFuncAttributeMaxDynamicSharedMemorySize, ATTN_SMEM);

    // 1. all weight conversions in one launch
    f2bf_all<<<192, 256>>>(qkv_w, proj_w, fc1_w, fc2_w, wq, wp, w1, w2);
    // 2. fused LN1 + shift/window gather + QKV GEMM -> bf16 qkv (+ V lo plane)
    qkv_fused<<<MROWS / 128, 256, FUSED_SMEM>>>(x, n1g, n1b, wq, qkv_b, qkvb, vlo);
    // 3. tensor-core window attention (split P/V) -> bf16
    attn_kernel<<<NWB, 256, ATTN_SMEM>>>(qkvb, vlo, rpb, attnb);
    // 4. proj GEMM + gather + residual(x) + fused LN2 -> x1 (f32), xn2 (bf16)
    bgemm<1, 3><<<dim3(MROWS / 128, 1), 256, GEMM_SMEM>>>(attnb, wp, proj_b, x, x1, xn2, n2g, n2b, 128, 128);
    // 5. fused fc1 GEMM (A resident) + GELU -> bf16
    fc1_fused<<<MROWS / 128, 256, FUSED_SMEM>>>(xn2, w1, fc1_b, hb);
    // 6. fc2 GEMM + residual(x1) -> out
    bgemm<0, 2><<<dim3(MROWS / 128, 1), 256, GEMM_SMEM>>>(hb, w2, fc2_b, x1, out, nullptr, nullptr, nullptr, 512, 128);
}

// round 7
// speedup vs baseline: 5.6155x; 1.0355x over previous
#include <cuda_runtime.h>
#include <cuda_bf16.h>
#include <stdint.h>
#include <math.h>

// ---------------- problem constants ----------------
#define BATCH 64
#define HDIM 56
#define WDIM 56
#define CDIM 128
#define NHEAD 4
#define WSZ 7
#define SHIFT 3
#define NTOK 49
#define NWIN 64
#define NWB (BATCH * NWIN)
#define MROWS (NWB * NTOK)   // 200704
#define HID 512

// ---------------- scratch ----------------
__device__ __align__(256) __nv_bfloat16 g_qkv[(size_t)MROWS * 3 * CDIM];
__device__ __align__(256) __nv_bfloat16 g_vlo[(size_t)MROWS * CDIM];
__device__ __align__(256) __nv_bfloat16 g_attn[(size_t)MROWS * CDIM];
__device__ __align__(256) __nv_bfloat16 g_wq[3 * CDIM * CDIM];
__device__ __align__(256) __nv_bfloat16 g_wp[CDIM * CDIM];
__device__ __align__(256) __nv_bfloat16 g_w1[HID * CDIM];
__device__ __align__(256) __nv_bfloat16 g_w2[CDIM * HID];

// ---------------- tensor-core helpers ----------------
__device__ __forceinline__ void ldsm4(uint32_t& r0, uint32_t& r1, uint32_t& r2, uint32_t& r3,
                                      uint32_t addr) {
    asm volatile("ldmatrix.sync.aligned.m8n8.x4.shared.b16 {%0,%1,%2,%3}, [%4];"
                 : "=r"(r0), "=r"(r1), "=r"(r2), "=r"(r3) : "r"(addr));
}
__device__ __forceinline__ void ldsm4t(uint32_t& r0, uint32_t& r1, uint32_t& r2, uint32_t& r3,
                                       uint32_t addr) {
    asm volatile("ldmatrix.sync.aligned.m8n8.x4.trans.shared.b16 {%0,%1,%2,%3}, [%4];"
                 : "=r"(r0), "=r"(r1), "=r"(r2), "=r"(r3) : "r"(addr));
}
__device__ __forceinline__ void mma16816(float* c, const uint32_t* a, uint32_t b0, uint32_t b1) {
    asm volatile("mma.sync.aligned.m16n8k16.row.col.f32.bf16.bf16.f32 "
                 "{%0,%1,%2,%3}, {%4,%5,%6,%7}, {%8,%9}, {%0,%1,%2,%3};"
                 : "+f"(c[0]), "+f"(c[1]), "+f"(c[2]), "+f"(c[3])
                 : "r"(a[0]), "r"(a[1]), "r"(a[2]), "r"(a[3]), "r"(b0), "r"(b1));
}
__device__ __forceinline__ uint32_t pack_bf2(float a, float b) {
    __nv_bfloat162 t = __floats2bfloat162_rn(a, b);
    return *(uint32_t*)&t;
}
#define CP_ASYNC16(dst, src) asm volatile("cp.async.cg.shared.global [%0], [%1], 16;" :: "r"(dst), "l"(src))
#define CP_COMMIT() asm volatile("cp.async.commit_group;")

// 128x128x64 micro-step: sa/sb are 128-row x 64-col bf16 tiles (144B row stride)
__device__ __forceinline__ void mma_tile(const unsigned char* sa, const unsigned char* sb,
                                         int wm, int wn, int lane, float acc[2][8][4]) {
    const int mat = lane >> 3, l7 = lane & 7;
    #pragma unroll
    for (int ks = 0; ks < 4; ks++) {
        const int kc = ks * 2;
        uint32_t a[2][4];
        #pragma unroll
        for (int tm = 0; tm < 2; tm++) {
            int r = wm * 32 + tm * 16 + (mat & 1) * 8 + l7;
            int c = kc + (mat >> 1);
            ldsm4(a[tm][0], a[tm][1], a[tm][2], a[tm][3],
                  (uint32_t)__cvta_generic_to_shared(sa + r * 144 + c * 16));
        }
        uint32_t b[4][4];
        #pragma unroll
        for (int tn2 = 0; tn2 < 4; tn2++) {
            int n = wn * 64 + tn2 * 16 + (mat >> 1) * 8 + l7;
            int c = kc + (mat & 1);
            ldsm4(b[tn2][0], b[tn2][1], b[tn2][2], b[tn2][3],
                  (uint32_t)__cvta_generic_to_shared(sb + n * 144 + c * 16));
        }
        #pragma unroll
        for (int tm = 0; tm < 2; tm++)
            #pragma unroll
            for (int tn = 0; tn < 8; tn++)
                mma16816(acc[tm][tn], a[tm], b[tn >> 1][(tn & 1) * 2], b[tn >> 1][(tn & 1) * 2 + 1]);
    }
}

// ---------------- fp32 -> bf16 all four weights, one launch ----------------
__global__ void f2bf_all(const float* __restrict__ wq, const float* __restrict__ wp,
                         const float* __restrict__ w1, const float* __restrict__ w2,
                         __nv_bfloat16* oq, __nv_bfloat16* op,
                         __nv_bfloat16* o1, __nv_bfloat16* o2) {
    int i = blockIdx.x * 256 + threadIdx.x;   // float4 index; total 49152
    const float* src; __nv_bfloat16* dst; int off;
    if (i < 12288)      { src = wq; dst = oq; off = i; }
    else if (i < 16384) { src = wp; dst = op; off = i - 12288; }
    else if (i < 32768) { src = w1; dst = o1; off = i - 16384; }
    else                { src = w2; dst = o2; off = i - 32768; }
    float4 v = ((const float4*)src)[off];
    __nv_bfloat162* o = ((__nv_bfloat162*)dst) + off * 2;
    o[0] = __floats2bfloat162_rn(v.x, v.y);
    o[1] = __floats2bfloat162_rn(v.z, v.w);
}

// ---------------- fused LN1(+shift/window gather) + QKV GEMM ----------------
// smem: A0 @0, A1 @18432, Bbuf0 @36864, Bbuf1 @55296. total 73728.
__global__ void __launch_bounds__(256, 2)
qkv_fused(const float* __restrict__ x, const float* __restrict__ g1, const float* __restrict__ b1,
          const __nv_bfloat16* __restrict__ W, const float* __restrict__ bias,
          __nv_bfloat16* __restrict__ out, __nv_bfloat16* __restrict__ vlo) {
    extern __shared__ unsigned char smem[];
    const int tid = threadIdx.x;
    const int bR = blockIdx.x;
    const int warp = tid >> 5, lane = tid & 31;
    const int wm = warp & 3, wn = warp >> 2;
    const int ldrow = tid >> 3, ldpos = tid & 7;

    auto loadB = [&](int buf, int nt, int kt) {
        unsigned char* sb = smem + 36864 + buf * 18432;
        #pragma unroll
        for (int it = 0; it < 4; it++) {
            int row = ldrow + it * 32;
            uint32_t d = (uint32_t)__cvta_generic_to_shared(sb + row * 144 + ldpos * 16);
            CP_ASYNC16(d, W + (size_t)(nt * 128 + row) * 128 + kt * 64 + ldpos * 8);
        }
        CP_COMMIT();
    };

    loadB(0, 0, 0);
    loadB(1, 0, 1);

    // LN1 + gather into A tiles (warp w -> rows w*16..w*16+15)
    {
        float4 gv = ((const float4*)g1)[lane & 31];
        float4 bv = ((const float4*)b1)[lane & 31];
        unsigned char* At = smem + ((lane & 16) ? 18432 : 0);
        int off = (lane & 15) * 8;
        #pragma unroll 2
        for (int t = 0; t < 16; t++) {
            int row = warp * 16 + t;
            int r = bR * 128 + row;
            int widx = r / NTOK, n = r - widx * NTOK;
            int b = widx >> 6, wi = widx & 63;
            int wh = wi >> 3, ww = wi & 7;
            int i = n / 7, j = n - i * 7;
            int sh = wh * 7 + i + SHIFT; if (sh >= HDIM) sh -= HDIM;
            int sw = ww * 7 + j + SHIFT; if (sw >= WDIM) sw -= WDIM;
            long srow = (long)b * (HDIM * WDIM) + sh * WDIM + sw;
            float4 v = ((const float4*)(x + srow * (long)CDIM))[lane];
            float s = v.x + v.y + v.z + v.w;
            float sq = v.x * v.x + v.y * v.y + v.z * v.z + v.w * v.w;
            #pragma unroll
            for (int o = 16; o; o >>= 1) {
                s  += __shfl_xor_sync(0xFFFFFFFFu, s, o);
                sq += __shfl_xor_sync(0xFFFFFFFFu, sq, o);
            }
            float mu = s * (1.0f / 128.0f);
            float var = sq * (1.0f / 128.0f) - mu * mu;
            float inv = rsqrtf(var + 1e-5f);
            float r0 = (v.x - mu) * inv * gv.x + bv.x;
            float r1 = (v.y - mu) * inv * gv.y + bv.y;
            float r2 = (v.z - mu) * inv * gv.z + bv.z;
            float r3 = (v.w - mu) * inv * gv.w + bv.w;
            *(uint32_t*)(At + row * 144 + off)     = pack_bf2(r0, r1);
            *(uint32_t*)(At + row * 144 + off + 4) = pack_bf2(r2, r3);
        }
    }

    const int gr = lane >> 2, gc = (lane & 3) * 2;
    for (int nt = 0; nt < 3; nt++) {
        float acc[2][8][4];
        #pragma unroll
        for (int i = 0; i < 2; i++)
            #pragma unroll
            for (int j = 0; j < 8; j++)
                #pragma unroll
                for (int q = 0; q < 4; q++) acc[i][j][q] = 0.0f;
        #pragma unroll
        for (int kt = 0; kt < 2; kt++) {
            int idx = nt * 2 + kt;
            if (idx < 5) asm volatile("cp.async.wait_group 1;");
            else         asm volatile("cp.async.wait_group 0;");
            __syncthreads();
            mma_tile(smem + kt * 18432, smem + 36864 + (idx & 1) * 18432, wm, wn, lane, acc);
            __syncthreads();
            if (idx + 2 < 6) loadB(idx & 1, (idx + 2) >> 1, (idx + 2) & 1);
        }
        // epilogue: bias + bf16 store (nt==2 also writes V residual plane)
        #pragma unroll
        for (int tm = 0; tm < 2; tm++) {
            #pragma unroll
            for (int tn = 0; tn < 8; tn++) {
                int col = nt * 128 + wn * 64 + tn * 8 + gc;
                float bs0 = bias[col], bs1 = bias[col + 1];
                int row0 = bR * 128 + wm * 32 + tm * 16 + gr;
                float v0 = acc[tm][tn][0] + bs0, v1 = acc[tm][tn][1] + bs1;
                float v2 = acc[tm][tn][2] + bs0, v3 = acc[tm][tn][3] + bs1;
                uint32_t u0 = pack_bf2(v0, v1), u1 = pack_bf2(v2, v3);
                *(uint32_t*)(out + (size_t)row0 * 384 + col) = u0;
                *(uint32_t*)(out + (size_t)(row0 + 8) * 384 + col) = u1;
                if (nt == 2) {
                    int lc = col - 256;
                    float h0 = __uint_as_float(u0 << 16), h1 = __uint_as_float(u0 & 0xFFFF0000u);
                    float h2 = __uint_as_float(u1 << 16), h3 = __uint_as_float(u1 & 0xFFFF0000u);
                    *(uint32_t*)(vlo + (size_t)row0 * CDIM + lc) = pack_bf2(v0 - h0, v1 - h1);
                    *(uint32_t*)(vlo + (size_t)(row0 + 8) * CDIM + lc) = pack_bf2(v2 - h2, v3 - h3);
                }
            }
        }
    }
}

// ---------------- fused second half: proj + resid + LN2 + fc1 + GELU + fc2 + resid ----
// smem layout:
//   A/xn2 sub0 @0, sub1 @18432; W dbl-buf @36864,@55296; h sub0 @73728, sub1 @92160;
//   x1 f32[128][136] @110592 (69632); red float2[256] @180224; rowmap @182272. total 182784.
#define MF_W0 36864
#define MF_H0 73728
#define MF_X1 110592
#define MF_RED 180224
#define MF_ROWMAP 182272
#define MLP_SMEM 182784

__global__ void __launch_bounds__(256, 1)
mlp_fused(const __nv_bfloat16* __restrict__ A, const float* __restrict__ resid,
          const __nv_bfloat16* __restrict__ Wp, const float* __restrict__ bp,
          const float* __restrict__ g2, const float* __restrict__ b2,
          const __nv_bfloat16* __restrict__ W1, const float* __restrict__ b1,
          const __nv_bfloat16* __restrict__ W2, const float* __restrict__ b2b,
          float* __restrict__ out) {
    extern __shared__ unsigned char smem[];
    int* rowmap = (int*)(smem + MF_ROWMAP);
    float2* red = (float2*)(smem + MF_RED);
    float* x1s = (float*)(smem + MF_X1);       // stride 136 floats
    const int tid = threadIdx.x;
    const int bR = blockIdx.x;
    const int warp = tid >> 5, lane = tid & 31;
    const int wm = warp & 3, wn = warp >> 2;
    const int ldrow = tid >> 3, ldpos = tid & 7;
    const int gr = lane >> 2, gc = (lane & 3) * 2;

    if (tid < 128) {
        int r = bR * 128 + tid;
        int b = r / (HDIM * WDIM);
        int l = r - b * (HDIM * WDIM);
        int h = l / WDIM, w = l - h * WDIM;
        int sh = h - SHIFT; if (sh < 0) sh += HDIM;
        int sw = w - SHIFT; if (sw < 0) sw += WDIM;
        int wh = sh / 7, i = sh - wh * 7;
        int ww = sw / 7, j = sw - ww * 7;
        rowmap[tid] = ((b * 64 + wh * 8 + ww) * 49 + i * 7 + j);
    }
    __syncthreads();

    // A prefetch (gathered attention-output rows), one group
    #pragma unroll
    for (int kt = 0; kt < 2; kt++)
        #pragma unroll
        for (int it = 0; it < 4; it++) {
            int row = ldrow + it * 32;
            uint32_t d = (uint32_t)__cvta_generic_to_shared(smem + kt * 18432 + row * 144 + ldpos * 16);
            CP_ASYNC16(d, A + (size_t)rowmap[row] * CDIM + kt * 64 + ldpos * 8);
        }
    CP_COMMIT();

    // weight tile stream: s=0,1 proj; then per nt: 2x W1[nt], 2x W2[k=nt*128+..]
    auto loadW = [&](int s) {
        const __nv_bfloat16* base; int ld;
        if (s < 2) { base = Wp + s * 64; ld = 128; }
        else {
            int t = s - 2, nt = t >> 2, q = t & 3;
            if (q < 2) { base = W1 + (size_t)(nt * 128) * 128 + q * 64; ld = 128; }
            else       { base = W2 + nt * 128 + (q - 2) * 64; ld = 512; }
        }
        unsigned char* sb = smem + MF_W0 + (s & 1) * 18432;
        #pragma unroll
        for (int it = 0; it < 4; it++) {
            int row = ldrow + it * 32;
            uint32_t d = (uint32_t)__cvta_generic_to_shared(sb + row * 144 + ldpos * 16);
            CP_ASYNC16(d, base + (size_t)row * ld + ldpos * 8);
        }
        CP_COMMIT();
    };
    loadW(0); loadW(1);

    auto stepWait = [&](int s) {
        if (s < 17) asm volatile("cp.async.wait_group 1;");
        else        asm volatile("cp.async.wait_group 0;");
    };

    float acc2[2][8][4];
    #pragma unroll
    for (int i = 0; i < 2; i++)
        #pragma unroll
        for (int j = 0; j < 8; j++)
            #pragma unroll
            for (int q = 0; q < 4; q++) acc2[i][j][q] = 0.0f;

    // ---- proj GEMM (K=128) ----
    {
        float acc1[2][8][4];
        #pragma unroll
        for (int i = 0; i < 2; i++)
            #pragma unroll
            for (int j = 0; j < 8; j++)
                #pragma unroll
                for (int q = 0; q < 4; q++) acc1[i][j][q] = 0.0f;
        #pragma unroll
        for (int kt = 0; kt < 2; kt++) {
            int s = kt;
            stepWait(s); __syncthreads();
            mma_tile(smem + kt * 18432, smem + MF_W0 + (s & 1) * 18432, wm, wn, lane, acc1);
            __syncthreads();
            loadW(s + 2);
        }
        // epilogue: + bias + resid -> x1 (smem); row stats; LN2 -> xn2 (A tiles)
        float psum[2][2], psq[2][2];
        #pragma unroll
        for (int tm = 0; tm < 2; tm++)
            #pragma unroll
            for (int sl = 0; sl < 2; sl++) { psum[tm][sl] = 0.0f; psq[tm][sl] = 0.0f; }
        #pragma unroll
        for (int tm = 0; tm < 2; tm++) {
            #pragma unroll
            for (int tn = 0; tn < 8; tn++) {
                int col = wn * 64 + tn * 8 + gc;
                float bs0 = bp[col], bs1 = bp[col + 1];
                int lrow0 = wm * 32 + tm * 16 + gr;
                size_t grow0 = (size_t)(bR * 128 + lrow0);
                float2 r0 = *(const float2*)(resid + grow0 * CDIM + col);
                float2 r1 = *(const float2*)(resid + (grow0 + 8) * CDIM + col);
                float v0 = acc1[tm][tn][0] + bs0 + r0.x;
                float v1 = acc1[tm][tn][1] + bs1 + r0.y;
                float v2 = acc1[tm][tn][2] + bs0 + r1.x;
                float v3 = acc1[tm][tn][3] + bs1 + r1.y;
                acc1[tm][tn][0] = v0; acc1[tm][tn][1] = v1;
                acc1[tm][tn][2] = v2; acc1[tm][tn][3] = v3;
                *(float2*)(x1s + lrow0 * 136 + col) = make_float2(v0, v1);
                *(float2*)(x1s + (lrow0 + 8) * 136 + col) = make_float2(v2, v3);
                psum[tm][0] += v0 + v1;  psq[tm][0] += v0 * v0 + v1 * v1;
                psum[tm][1] += v2 + v3;  psq[tm][1] += v2 * v2 + v3 * v3;
            }
        }
        #pragma unroll
        for (int tm = 0; tm < 2; tm++)
            #pragma unroll
            for (int sl = 0; sl < 2; sl++) {
                float s = psum[tm][sl], q = psq[tm][sl];
                s += __shfl_xor_sync(0xFFFFFFFFu, s, 1); q += __shfl_xor_sync(0xFFFFFFFFu, q, 1);
                s += __shfl_xor_sync(0xFFFFFFFFu, s, 2); q += __shfl_xor_sync(0xFFFFFFFFu, q, 2);
                if ((lane & 3) == 0) red[wn * 128 + wm * 32 + tm * 16 + sl * 8 + gr] = make_float2(s, q);
            }
        __syncthreads();
        #pragma unroll
        for (int tm = 0; tm < 2; tm++) {
            #pragma unroll
            for (int sl = 0; sl < 2; sl++) {
                int lrow = wm * 32 + tm * 16 + sl * 8 + gr;
                float2 t0 = red[lrow], t1 = red[128 + lrow];
                float mu = (t0.x + t1.x) * (1.0f / 128.0f);
                float var = (t0.y + t1.y) * (1.0f / 128.0f) - mu * mu;
                float inv = rsqrtf(var + 1e-5f);
                #pragma unroll
                for (int tn = 0; tn < 8; tn++) {
                    int col = wn * 64 + tn * 8 + gc;
                    float v0 = acc1[tm][tn][sl * 2 + 0], v1 = acc1[tm][tn][sl * 2 + 1];
                    float n0 = (v0 - mu) * inv * g2[col] + b2[col];
                    float n1 = (v1 - mu) * inv * g2[col + 1] + b2[col + 1];
                    // xn2 -> A tiles, ldmatrix layout
                    *(uint32_t*)(smem + (col >> 6) * 18432 + lrow * 144 + ((col & 63) >> 3) * 16 + (col & 7) * 2)
                        = pack_bf2(n0, n1);
                }
            }
        }
        __syncthreads();   // xn2 ready
    }

    // ---- MLP: interleaved fc1(nt) -> h tile -> fc2 partial ----
    const float is2 = 0.70710678118654752f;
    for (int nt = 0; nt < 4; nt++) {
        float acc1[2][8][4];
        #pragma unroll
        for (int i = 0; i < 2; i++)
            #pragma unroll
            for (int j = 0; j < 8; j++)
                #pragma unroll
                for (int q = 0; q < 4; q++) acc1[i][j][q] = 0.0f;
        #pragma unroll
        for (int kt = 0; kt < 2; kt++) {
            int s = 2 + nt * 4 + kt;
            stepWait(s); __syncthreads();
            mma_tile(smem + kt * 18432, smem + MF_W0 + (s & 1) * 18432, wm, wn, lane, acc1);
            __syncthreads();
            if (s + 2 < 18) loadW(s + 2);
        }
        // h epilogue: gelu(acc1 + b1) -> h tile (bf16, ldmatrix layout)
        #pragma unroll
        for (int tm = 0; tm < 2; tm++) {
            #pragma unroll
            for (int tn = 0; tn < 8; tn++) {
                int col = wn * 64 + tn * 8 + gc;          // local 0..127
                int colg = nt * 128 + col;
                float bs0 = b1[colg], bs1 = b1[colg + 1];
                int lrow0 = wm * 32 + tm * 16 + gr;
                float v0 = acc1[tm][tn][0] + bs0, v1 = acc1[tm][tn][1] + bs1;
                float v2 = acc1[tm][tn][2] + bs0, v3 = acc1[tm][tn][3] + bs1;
                v0 = 0.5f * v0 * (1.0f + erff(v0 * is2));
                v1 = 0.5f * v1 * (1.0f + erff(v1 * is2));
                v2 = 0.5f * v2 * (1.0f + erff(v2 * is2));
                v3 = 0.5f * v3 * (1.0f + erff(v3 * is2));
                int boff = (col >> 6) * 18432 + ((col & 63) >> 3) * 16 + (col & 7) * 2;
                *(uint32_t*)(smem + MF_H0 + boff + lrow0 * 144)       = pack_bf2(v0, v1);
                *(uint32_t*)(smem + MF_H0 + boff + (lrow0 + 8) * 144) = pack_bf2(v2, v3);
            }
        }
        __syncthreads();   // h visible
        #pragma unroll
        for (int q = 0; q < 2; q++) {
            int s = 4 + nt * 4 + q;
            stepWait(s); __syncthreads();
            mma_tile(smem + MF_H0 + q * 18432, smem + MF_W0 + (s & 1) * 18432, wm, wn, lane, acc2);
            __syncthreads();
            if (s + 2 < 18) loadW(s + 2);
        }
    }

    // ---- final epilogue: out = acc2 + b2b + x1 ----
    #pragma unroll
    for (int tm = 0; tm < 2; tm++) {
        #pragma unroll
        for (int tn = 0; tn < 8; tn++) {
            int col = wn * 64 + tn * 8 + gc;
            float bs0 = b2b[col], bs1 = b2b[col + 1];
            int lrow0 = wm * 32 + tm * 16 + gr;
            size_t grow0 = (size_t)(bR * 128 + lrow0);
            float2 x0 = *(const float2*)(x1s + lrow0 * 136 + col);
            float2 x1v = *(const float2*)(x1s + (lrow0 + 8) * 136 + col);
            float v0 = acc2[tm][tn][0] + bs0, v1 = acc2[tm][tn][1] + bs1;
            float v2 = acc2[tm][tn][2] + bs0, v3 = acc2[tm][tn][3] + bs1;
            *(float2*)(out + grow0 * CDIM + col)       = make_float2(v0 + x0.x, v1 + x0.y);
            *(float2*)(out + (grow0 + 8) * CDIM + col) = make_float2(v2 + x1v.x, v3 + x1v.y);
        }
    }
}

// ---------------- tensor-core window attention, split-precision P@V ----------------
__global__ void __launch_bounds__(256)
attn_kernel(const __nv_bfloat16* __restrict__ qkv, const __nv_bfloat16* __restrict__ vlo,
            const float* __restrict__ rpb, __nv_bfloat16* __restrict__ outw) {
    extern __shared__ unsigned char sm[];
    const int widx = blockIdx.x;
    const int tid = threadIdx.x;

    #pragma unroll
    for (int it = 0; it < 12; it++) {
        int idx = it * 256 + tid;
        int c4 = idx & 3, row = (idx >> 2) & 63, h = (idx >> 8) & 3, t = idx >> 10;
        uint4 v = make_uint4(0, 0, 0, 0);
        if (row < 49)
            v = *(const uint4*)(qkv + (size_t)widx * 18816 + row * 384 + t * 128 + h * 32 + c4 * 8);
        *(uint4*)(sm + h * 15360 + t * 5120 + row * 80 + c4 * 16) = v;
    }
    #pragma unroll
    for (int it = 0; it < 4; it++) {
        int idx = it * 256 + tid;
        int c4 = idx & 3, row = (idx >> 2) & 63, h = idx >> 8;
        uint4 v = make_uint4(0, 0, 0, 0);
        if (row < 49)
            v = *(const uint4*)(vlo + ((size_t)widx * 49 + row) * 128 + h * 32 + c4 * 8);
        *(uint4*)(sm + 61440 + h * 5120 + row * 80 + c4 * 16) = v;
    }
    float* rp = (float*)(sm + 81920);
    for (int p = tid; p < 676; p += 256) rp[p] = rpb[(p % 169) * 4 + (p / 169)];
    int* regs = (int*)(sm + 84624);
    signed char* i2t = (signed char*)(sm + 84880);
    signed char* j2t = (signed char*)(sm + 84944);
    if (tid < 64) { i2t[tid] = tid / 7; j2t[tid] = tid % 7; }
    if (tid < 49) {
        int wi = widx & 63;
        int wh = wi >> 3, ww = wi & 7;
        int i = tid / 7, j = tid - i * 7;
        int grr = wh * 7 + i, gcc = ww * 7 + j;
        int rr = grr < 49 ? 0 : (grr < 53 ? 1 : 2);
        int rc = gcc < 49 ? 0 : (gcc < 53 ? 1 : 2);
        regs[tid] = rr * 3 + rc;
    }
    __syncthreads();

    const int warp = tid >> 5, lane = tid & 31;
    const int h = warp >> 1, half = warp & 1;
    const int mat = lane >> 3, l7 = lane & 7, gr = lane >> 2, gc = (lane & 3) * 2;
    const unsigned char* Q = sm + h * 15360;
    const unsigned char* Kp = Q + 5120;
    const unsigned char* Vp = Q + 10240;
    const unsigned char* Vl = sm + 61440 + h * 5120;

    float sacc[2][8][4];
    #pragma unroll
    for (int i = 0; i < 2; i++)
        #pragma unroll
        for (int j = 0; j < 8; j++)
            #pragma unroll
            for (int q = 0; q < 4; q++) sacc[i][j][q] = 0.0f;

    #pragma unroll
    for (int kc = 0; kc < 2; kc++) {
        uint32_t a[2][4];
        #pragma unroll
        for (int tm = 0; tm < 2; tm++)
            ldsm4(a[tm][0], a[tm][1], a[tm][2], a[tm][3],
                  (uint32_t)__cvta_generic_to_shared(Q + (half * 32 + tm * 16 + (mat & 1) * 8 + l7) * 80 + kc * 32 + (mat >> 1) * 16));
        uint32_t b[4][4];
        #pragma unroll
        for (int tn2 = 0; tn2 < 4; tn2++)
            ldsm4(b[tn2][0], b[tn2][1], b[tn2][2], b[tn2][3],
                  (uint32_t)__cvta_generic_to_shared(Kp + (tn2 * 16 + (mat >> 1) * 8 + l7) * 80 + kc * 32 + (mat & 1) * 16));
        #pragma unroll
        for (int tm = 0; tm < 2; tm++)
            #pragma unroll
            for (int tn = 0; tn < 8; tn++)
                mma16816(sacc[tm][tn], a[tm], b[tn >> 1][(tn & 1) * 2], b[tn >> 1][(tn & 1) * 2 + 1]);
    }

    const float scale = 0.17677669529663687f;
    uint32_t pa[2][4][4], pl[2][4][4];
    #pragma unroll
    for (int tm = 0; tm < 2; tm++) {
        #pragma unroll
        for (int slot = 0; slot < 2; slot++) {
            int n = half * 32 + tm * 16 + gr + slot * 8;
            bool valid = n < 49;
            int i1 = 0, j1 = 0, regn = 0;
            if (valid) { i1 = i2t[n]; j1 = j2t[n]; regn = regs[n]; }
            float vv[16];
            float mx = -1e30f;
            #pragma unroll
            for (int tn = 0; tn < 8; tn++) {
                #pragma unroll
                for (int e = 0; e < 2; e++) {
                    int m = tn * 8 + gc + e;
                    float v = -1e30f;
                    if (valid && m < 49) {
                        v = sacc[tm][tn][slot * 2 + e] * scale
                          + rp[h * 169 + (i1 - i2t[m] + 6) * 13 + (j1 - j2t[m] + 6)];
                        if (regs[m] != regn) v -= 100.0f;
                    }
                    vv[tn * 2 + e] = v;
                    mx = fmaxf(mx, v);
                }
            }
            mx = fmaxf(mx, __shfl_xor_sync(0xFFFFFFFFu, mx, 1));
            mx = fmaxf(mx, __shfl_xor_sync(0xFFFFFFFFu, mx, 2));
            float sum = 0.0f;
            #pragma unroll
            for (int i = 0; i < 16; i++) { vv[i] = __expf(vv[i] - mx); sum += vv[i]; }
            sum += __shfl_xor_sync(0xFFFFFFFFu, sum, 1);
            sum += __shfl_xor_sync(0xFFFFFFFFu, sum, 2);
            float inv = valid ? __frcp_rn(sum) : 0.0f;
            #pragma unroll
            for (int tn = 0; tn < 8; tn++) {
                float p0 = vv[tn * 2] * inv, p1 = vv[tn * 2 + 1] * inv;
                uint32_t u = pack_bf2(p0, p1);
                pa[tm][tn >> 1][(tn & 1) * 2 + slot] = u;
                float h0 = __uint_as_float(u << 16), h1 = __uint_as_float(u & 0xFFFF0000u);
                pl[tm][tn >> 1][(tn & 1) * 2 + slot] = pack_bf2(p0 - h0, p1 - h1);
            }
        }
    }

    float oacc[2][4][4];
    #pragma unroll
    for (int i = 0; i < 2; i++)
        #pragma unroll
        for (int j = 0; j < 4; j++)
            #pragma unroll
            for (int q = 0; q < 4; q++) oacc[i][j][q] = 0.0f;

    #pragma unroll
    for (int kk = 0; kk < 4; kk++) {
        uint32_t bh[2][4], bl[2][4];
        #pragma unroll
        for (int dd = 0; dd < 2; dd++) {
            ldsm4t(bh[dd][0], bh[dd][1], bh[dd][2], bh[dd][3],
                   (uint32_t)__cvta_generic_to_shared(Vp + (kk * 16 + (mat & 1) * 8 + l7) * 80 + dd * 32 + (mat >> 1) * 16));
            ldsm4t(bl[dd][0], bl[dd][1], bl[dd][2], bl[dd][3],
                   (uint32_t)__cvta_generic_to_shared(Vl + (kk * 16 + (mat & 1) * 8 + l7) * 80 + dd * 32 + (mat >> 1) * 16));
        }
        #pragma unroll
        for (int tm = 0; tm < 2; tm++) {
            #pragma unroll
            for (int dd = 0; dd < 2; dd++) {
                mma16816(oacc[tm][dd * 2 + 0], pa[tm][kk], bh[dd][0], bh[dd][1]);
                mma16816(oacc[tm][dd * 2 + 0], pl[tm][kk], bh[dd][0], bh[dd][1]);
                mma16816(oacc[tm][dd * 2 + 0], pa[tm][kk], bl[dd][0], bl[dd][1]);
                mma16816(oacc[tm][dd * 2 + 1], pa[tm][kk], bh[dd][2], bh[dd][3]);
                mma16816(oacc[tm][dd * 2 + 1], pl[tm][kk], bh[dd][2], bh[dd][3]);
                mma16816(oacc[tm][dd * 2 + 1], pa[tm][kk], bl[dd][2], bl[dd][3]);
            }
        }
    }

    #pragma unroll
    for (int tm = 0; tm < 2; tm++) {
        int n0 = half * 32 + tm * 16 + gr;
        #pragma unroll
        for (int dt = 0; dt < 4; dt++) {
            int col = h * 32 + dt * 8 + gc;
            if (n0 < 49)
                *(__nv_bfloat162*)(outw + ((size_t)widx * 49 + n0) * 128 + col) =
                    __floats2bfloat162_rn(oacc[tm][dt][0], oacc[tm][dt][1]);
            if (n0 + 8 < 49)
                *(__nv_bfloat162*)(outw + ((size_t)widx * 49 + n0 + 8) * 128 + col) =
                    __floats2bfloat162_rn(oacc[tm][dt][2], oacc[tm][dt][3]);
        }
    }
}

// ---------------- launch ----------------
#define FUSED_SMEM 73728
#define ATTN_SMEM 85008

extern "C" void kernel_launch(void* const* d_in, const int* in_sizes, int n_in,
                              void* d_out, int out_size) {
    const float* x      = (const float*)d_in[0];
    const float* n1g    = (const float*)d_in[1];
    const float* n1b    = (const float*)d_in[2];
    const float* qkv_w  = (const float*)d_in[3];
    const float* qkv_b  = (const float*)d_in[4];
    const float* proj_w = (const float*)d_in[5];
    const float* proj_b = (const float*)d_in[6];
    const float* rpb    = (const float*)d_in[7];
    const float* n2g    = (const float*)d_in[8];
    const float* n2b    = (const float*)d_in[9];
    const float* fc1_w  = (const float*)d_in[10];
    const float* fc1_b  = (const float*)d_in[11];
    const float* fc2_w  = (const float*)d_in[12];
    const float* fc2_b  = (const float*)d_in[13];
    float* out = (float*)d_out;

    __nv_bfloat16 *qkvb, *vlo, *attnb, *wq, *wp, *w1, *w2;
    cudaGetSymbolAddress((void**)&qkvb, g_qkv);
    cudaGetSymbolAddress((void**)&vlo,  g_vlo);
    cudaGetSymbolAddress((void**)&attnb,g_attn);
    cudaGetSymbolAddress((void**)&wq,   g_wq);
    cudaGetSymbolAddress((void**)&wp,   g_wp);
    cudaGetSymbolAddress((void**)&w1,   g_w1);
    cudaGetSymbolAddress((void**)&w2,   g_w2);

    cudaFuncSetAttribute((const void*)qkv_fused, cudaFuncAttributeMaxDynamicSharedMemorySize, FUSED_SMEM);
    cudaFuncSetAttribute((const void*)attn_kernel, cudaFuncAttributeMaxDynamicSharedMemorySize, ATTN_SMEM);
    cudaFuncSetAttribute((const void*)mlp_fused, cudaFuncAttributeMaxDynamicSharedMemorySize, MLP_SMEM);

    // 1. all weight conversions in one launch
    f2bf_all<<<192, 256>>>(qkv_w, proj_w, fc1_w, fc2_w, wq, wp, w1, w2);
    // 2. fused LN1 + shift/window gather + QKV GEMM -> bf16 qkv (+ V lo plane)
    qkv_fused<<<MROWS / 128, 256, FUSED_SMEM>>>(x, n1g, n1b, wq, qkv_b, qkvb, vlo);
    // 3. tensor-core window attention (split P/V) -> bf16
    attn_kernel<<<NWB, 256, ATTN_SMEM>>>(qkvb, vlo, rpb, attnb);
    // 4. fused proj + resid + LN2 + fc1 + GELU + fc2 + resid -> out
    mlp_fused<<<MROWS / 128, 256, MLP_SMEM>>>(attnb, x, wp, proj_b, n2g, n2b,
                                              w1, fc1_b, w2, fc2_b, out);
}

// round 9
// speedup vs baseline: 5.9564x; 1.0607x over previous
#include <cuda_runtime.h>
#include <cuda_bf16.h>
#include <stdint.h>
#include <math.h>

// ---------------- problem constants ----------------
#define BATCH 64
#define HDIM 56
#define WDIM 56
#define CDIM 128
#define NHEAD 4
#define WSZ 7
#define SHIFT 3
#define NTOK 49
#define NWIN 64
#define NWB (BATCH * NWIN)
#define MROWS (NWB * NTOK)   // 200704
#define HID 512

// ---------------- scratch ----------------
__device__ __align__(256) __nv_bfloat16 g_qkv[(size_t)MROWS * 3 * CDIM];
__device__ __align__(256) __nv_bfloat16 g_vlo[(size_t)MROWS * CDIM];
__device__ __align__(256) __nv_bfloat16 g_attn[(size_t)MROWS * CDIM];
__device__ __align__(256) __nv_bfloat16 g_wq[3 * CDIM * CDIM];
__device__ __align__(256) __nv_bfloat16 g_wp[CDIM * CDIM];
__device__ __align__(256) __nv_bfloat16 g_w1[HID * CDIM];
__device__ __align__(256) __nv_bfloat16 g_w2[CDIM * HID];

// ---------------- tensor-core helpers ----------------
__device__ __forceinline__ void ldsm4(uint32_t& r0, uint32_t& r1, uint32_t& r2, uint32_t& r3,
                                      uint32_t addr) {
    asm volatile("ldmatrix.sync.aligned.m8n8.x4.shared.b16 {%0,%1,%2,%3}, [%4];"
                 : "=r"(r0), "=r"(r1), "=r"(r2), "=r"(r3) : "r"(addr));
}
__device__ __forceinline__ void ldsm4t(uint32_t& r0, uint32_t& r1, uint32_t& r2, uint32_t& r3,
                                       uint32_t addr) {
    asm volatile("ldmatrix.sync.aligned.m8n8.x4.trans.shared.b16 {%0,%1,%2,%3}, [%4];"
                 : "=r"(r0), "=r"(r1), "=r"(r2), "=r"(r3) : "r"(addr));
}
__device__ __forceinline__ void mma16816(float* c, const uint32_t* a, uint32_t b0, uint32_t b1) {
    asm volatile("mma.sync.aligned.m16n8k16.row.col.f32.bf16.bf16.f32 "
                 "{%0,%1,%2,%3}, {%4,%5,%6,%7}, {%8,%9}, {%0,%1,%2,%3};"
                 : "+f"(c[0]), "+f"(c[1]), "+f"(c[2]), "+f"(c[3])
                 : "r"(a[0]), "r"(a[1]), "r"(a[2]), "r"(a[3]), "r"(b0), "r"(b1));
}
__device__ __forceinline__ uint32_t pack_bf2(float a, float b) {
    __nv_bfloat162 t = __floats2bfloat162_rn(a, b);
    return *(uint32_t*)&t;
}
#define CP_ASYNC16(dst, src) asm volatile("cp.async.cg.shared.global [%0], [%1], 16;" :: "r"(dst), "l"(src))
#define CP_COMMIT() asm volatile("cp.async.commit_group;")

// MxNx64 micro-step: sa = M-row x 64-col bf16 tile, sb = N-row x 64-col (144B row stride).
// warp covers rows wm*32..+31, cols wn*64..+63. Valid for wm in {0..3} (128-row) or {0,1} (64-row).
__device__ __forceinline__ void mma_tile(const unsigned char* sa, const unsigned char* sb,
                                         int wm, int wn, int lane, float acc[2][8][4]) {
    const int mat = lane >> 3, l7 = lane & 7;
    #pragma unroll
    for (int ks = 0; ks < 4; ks++) {
        const int kc = ks * 2;
        uint32_t a[2][4];
        #pragma unroll
        for (int tm = 0; tm < 2; tm++) {
            int r = wm * 32 + tm * 16 + (mat & 1) * 8 + l7;
            int c = kc + (mat >> 1);
            ldsm4(a[tm][0], a[tm][1], a[tm][2], a[tm][3],
                  (uint32_t)__cvta_generic_to_shared(sa + r * 144 + c * 16));
        }
        uint32_t b[4][4];
        #pragma unroll
        for (int tn2 = 0; tn2 < 4; tn2++) {
            int n = wn * 64 + tn2 * 16 + (mat >> 1) * 8 + l7;
            int c = kc + (mat & 1);
            ldsm4(b[tn2][0], b[tn2][1], b[tn2][2], b[tn2][3],
                  (uint32_t)__cvta_generic_to_shared(sb + n * 144 + c * 16));
        }
        #pragma unroll
        for (int tm = 0; tm < 2; tm++)
            #pragma unroll
            for (int tn = 0; tn < 8; tn++)
                mma16816(acc[tm][tn], a[tm], b[tn >> 1][(tn & 1) * 2], b[tn >> 1][(tn & 1) * 2 + 1]);
    }
}

// ---------------- fp32 -> bf16 all four weights, one launch ----------------
__global__ void f2bf_all(const float* __restrict__ wq, const float* __restrict__ wp,
                         const float* __restrict__ w1, const float* __restrict__ w2,
                         __nv_bfloat16* oq, __nv_bfloat16* op,
                         __nv_bfloat16* o1, __nv_bfloat16* o2) {
    int i = blockIdx.x * 256 + threadIdx.x;   // float4 index; total 49152
    const float* src; __nv_bfloat16* dst; int off;
    if (i < 12288)      { src = wq; dst = oq; off = i; }
    else if (i < 16384) { src = wp; dst = op; off = i - 12288; }
    else if (i < 32768) { src = w1; dst = o1; off = i - 16384; }
    else                { src = w2; dst = o2; off = i - 32768; }
    float4 v = ((const float4*)src)[off];
    __nv_bfloat162* o = ((__nv_bfloat162*)dst) + off * 2;
    o[0] = __floats2bfloat162_rn(v.x, v.y);
    o[1] = __floats2bfloat162_rn(v.z, v.w);
}

// ---------------- fused LN1(+shift/window gather) + QKV GEMM ----------------
// smem: A0 @0, A1 @18432, Bbuf0 @36864, Bbuf1 @55296. total 73728.
__global__ void __launch_bounds__(256, 2)
qkv_fused(const float* __restrict__ x, const float* __restrict__ g1, const float* __restrict__ b1,
          const __nv_bfloat16* __restrict__ W, const float* __restrict__ bias,
          __nv_bfloat16* __restrict__ out, __nv_bfloat16* __restrict__ vlo) {
    extern __shared__ unsigned char smem[];
    const int tid = threadIdx.x;
    const int bR = blockIdx.x;
    const int warp = tid >> 5, lane = tid & 31;
    const int wm = warp & 3, wn = warp >> 2;
    const int ldrow = tid >> 3, ldpos = tid & 7;

    auto loadB = [&](int buf, int nt, int kt) {
        unsigned char* sb = smem + 36864 + buf * 18432;
        #pragma unroll
        for (int it = 0; it < 4; it++) {
            int row = ldrow + it * 32;
            uint32_t d = (uint32_t)__cvta_generic_to_shared(sb + row * 144 + ldpos * 16);
            CP_ASYNC16(d, W + (size_t)(nt * 128 + row) * 128 + kt * 64 + ldpos * 8);
        }
        CP_COMMIT();
    };

    loadB(0, 0, 0);
    loadB(1, 0, 1);

    // LN1 + gather into A tiles (warp w -> rows w*16..w*16+15)
    {
        float4 gv = ((const float4*)g1)[lane & 31];
        float4 bv = ((const float4*)b1)[lane & 31];
        unsigned char* At = smem + ((lane & 16) ? 18432 : 0);
        int off = (lane & 15) * 8;
        #pragma unroll 2
        for (int t = 0; t < 16; t++) {
            int row = warp * 16 + t;
            int r = bR * 128 + row;
            int widx = r / NTOK, n = r - widx * NTOK;
            int b = widx >> 6, wi = widx & 63;
            int wh = wi >> 3, ww = wi & 7;
            int i = n / 7, j = n - i * 7;
            int sh = wh * 7 + i + SHIFT; if (sh >= HDIM) sh -= HDIM;
            int sw = ww * 7 + j + SHIFT; if (sw >= WDIM) sw -= WDIM;
            long srow = (long)b * (HDIM * WDIM) + sh * WDIM + sw;
            float4 v = ((const float4*)(x + srow * (long)CDIM))[lane];
            float s = v.x + v.y + v.z + v.w;
            float sq = v.x * v.x + v.y * v.y + v.z * v.z + v.w * v.w;
            #pragma unroll
            for (int o = 16; o; o >>= 1) {
                s  += __shfl_xor_sync(0xFFFFFFFFu, s, o);
                sq += __shfl_xor_sync(0xFFFFFFFFu, sq, o);
            }
            float mu = s * (1.0f / 128.0f);
            float var = sq * (1.0f / 128.0f) - mu * mu;
            float inv = rsqrtf(var + 1e-5f);
            float r0 = (v.x - mu) * inv * gv.x + bv.x;
            float r1 = (v.y - mu) * inv * gv.y + bv.y;
            float r2 = (v.z - mu) * inv * gv.z + bv.z;
            float r3 = (v.w - mu) * inv * gv.w + bv.w;
            *(uint32_t*)(At + row * 144 + off)     = pack_bf2(r0, r1);
            *(uint32_t*)(At + row * 144 + off + 4) = pack_bf2(r2, r3);
        }
    }

    const int gr = lane >> 2, gc = (lane & 3) * 2;
    for (int nt = 0; nt < 3; nt++) {
        float acc[2][8][4];
        #pragma unroll
        for (int i = 0; i < 2; i++)
            #pragma unroll
            for (int j = 0; j < 8; j++)
                #pragma unroll
                for (int q = 0; q < 4; q++) acc[i][j][q] = 0.0f;
        #pragma unroll
        for (int kt = 0; kt < 2; kt++) {
            int idx = nt * 2 + kt;
            if (idx < 5) asm volatile("cp.async.wait_group 1;");
            else         asm volatile("cp.async.wait_group 0;");
            __syncthreads();
            mma_tile(smem + kt * 18432, smem + 36864 + (idx & 1) * 18432, wm, wn, lane, acc);
            __syncthreads();
            if (idx + 2 < 6) loadB(idx & 1, (idx + 2) >> 1, (idx + 2) & 1);
        }
        // epilogue: bias + bf16 store (nt==2 also writes V residual plane)
        #pragma unroll
        for (int tm = 0; tm < 2; tm++) {
            #pragma unroll
            for (int tn = 0; tn < 8; tn++) {
                int col = nt * 128 + wn * 64 + tn * 8 + gc;
                float bs0 = bias[col], bs1 = bias[col + 1];
                int row0 = bR * 128 + wm * 32 + tm * 16 + gr;
                float v0 = acc[tm][tn][0] + bs0, v1 = acc[tm][tn][1] + bs1;
                float v2 = acc[tm][tn][2] + bs0, v3 = acc[tm][tn][3] + bs1;
                uint32_t u0 = pack_bf2(v0, v1), u1 = pack_bf2(v2, v3);
                *(uint32_t*)(out + (size_t)row0 * 384 + col) = u0;
                *(uint32_t*)(out + (size_t)(row0 + 8) * 384 + col) = u1;
                if (nt == 2) {
                    int lc = col - 256;
                    float h0 = __uint_as_float(u0 << 16), h1 = __uint_as_float(u0 & 0xFFFF0000u);
                    float h2 = __uint_as_float(u1 << 16), h3 = __uint_as_float(u1 & 0xFFFF0000u);
                    *(uint32_t*)(vlo + (size_t)row0 * CDIM + lc) = pack_bf2(v0 - h0, v1 - h1);
                    *(uint32_t*)(vlo + (size_t)(row0 + 8) * CDIM + lc) = pack_bf2(v2 - h2, v3 - h3);
                }
            }
        }
    }
}

// ---------------- fused second half, 64-row CTA x 128 threads, 2 CTAs/SM ----------------
// proj + resid + LN2 + fc1 + GELU + fc2 + resid, all intermediates in smem.
// smem: A/xn2 sub0 @0, sub1 @9216; W dbl @18432,@36864; h sub0 @55296, sub1 @64512;
//       x1 f32[64][136] @73728 (34816); red float2[128] @108544; rowmap @109568. total 109824.
#define MG_W0 18432
#define MG_H0 55296
#define MG_X1 73728
#define MG_RED 108544
#define MG_ROWMAP 109568
#define MLP_SMEM 109824

__global__ void __launch_bounds__(128, 2)
mlp_fused(const __nv_bfloat16* __restrict__ A, const float* __restrict__ resid,
          const __nv_bfloat16* __restrict__ Wp, const float* __restrict__ bp,
          const float* __restrict__ g2, const float* __restrict__ b2,
          const __nv_bfloat16* __restrict__ W1, const float* __restrict__ b1,
          const __nv_bfloat16* __restrict__ W2, const float* __restrict__ b2b,
          float* __restrict__ out) {
    extern __shared__ unsigned char smem[];
    int* rowmap = (int*)(smem + MG_ROWMAP);
    float2* red = (float2*)(smem + MG_RED);
    float* x1s = (float*)(smem + MG_X1);       // stride 136 floats
    const int tid = threadIdx.x;
    const int bR = blockIdx.x;
    const int warp = tid >> 5, lane = tid & 31;
    const int wm = warp & 1, wn = warp >> 1;   // 2x2 warp grid, warp tile 32x64
    const int ldrow = tid >> 3, ldpos = tid & 7;
    const int gr = lane >> 2, gc = (lane & 3) * 2;

    if (tid < 64) {
        int r = bR * 64 + tid;
        int b = r / (HDIM * WDIM);
        int l = r - b * (HDIM * WDIM);
        int h = l / WDIM, w = l - h * WDIM;
        int sh = h - SHIFT; if (sh < 0) sh += HDIM;
        int sw = w - SHIFT; if (sw < 0) sw += WDIM;
        int wh = sh / 7, i = sh - wh * 7;
        int ww = sw / 7, j = sw - ww * 7;
        rowmap[tid] = ((b * 64 + wh * 8 + ww) * 49 + i * 7 + j);
    }
    __syncthreads();

    // A prefetch (gathered attention-output rows), one group
    #pragma unroll
    for (int kt = 0; kt < 2; kt++)
        #pragma unroll
        for (int it = 0; it < 4; it++) {
            int row = ldrow + it * 16;
            uint32_t d = (uint32_t)__cvta_generic_to_shared(smem + kt * 9216 + row * 144 + ldpos * 16);
            CP_ASYNC16(d, A + (size_t)rowmap[row] * CDIM + kt * 64 + ldpos * 8);
        }
    CP_COMMIT();

    // weight tile stream: s=0,1 proj; then per nt: 2x W1[nt], 2x W2[k=nt*128+..]
    auto loadW = [&](int s) {
        const __nv_bfloat16* base; int ld;
        if (s < 2) { base = Wp + s * 64; ld = 128; }
        else {
            int t = s - 2, nt = t >> 2, q = t & 3;
            if (q < 2) { base = W1 + (size_t)(nt * 128) * 128 + q * 64; ld = 128; }
            else       { base = W2 + nt * 128 + (q - 2) * 64; ld = 512; }
        }
        unsigned char* sb = smem + MG_W0 + (s & 1) * 18432;
        #pragma unroll
        for (int it = 0; it < 8; it++) {
            int row = ldrow + it * 16;
            uint32_t d = (uint32_t)__cvta_generic_to_shared(sb + row * 144 + ldpos * 16);
            CP_ASYNC16(d, base + (size_t)row * ld + ldpos * 8);
        }
        CP_COMMIT();
    };
    loadW(0); loadW(1);

    auto stepWait = [&](int s) {
        if (s < 17) asm volatile("cp.async.wait_group 1;");
        else        asm volatile("cp.async.wait_group 0;");
    };

    float acc2[2][8][4];
    #pragma unroll
    for (int i = 0; i < 2; i++)
        #pragma unroll
        for (int j = 0; j < 8; j++)
            #pragma unroll
            for (int q = 0; q < 4; q++) acc2[i][j][q] = 0.0f;

    // ---- proj GEMM (K=128) ----
    {
        float acc1[2][8][4];
        #pragma unroll
        for (int i = 0; i < 2; i++)
            #pragma unroll
            for (int j = 0; j < 8; j++)
                #pragma unroll
                for (int q = 0; q < 4; q++) acc1[i][j][q] = 0.0f;
        #pragma unroll
        for (int kt = 0; kt < 2; kt++) {
            int s = kt;
            stepWait(s); __syncthreads();
            mma_tile(smem + kt * 9216, smem + MG_W0 + (s & 1) * 18432, wm, wn, lane, acc1);
            __syncthreads();
            loadW(s + 2);
        }
        // epilogue: + bias + resid -> x1 (smem); row stats; LN2 -> xn2 (A tiles)
        float psum[2][2], psq[2][2];
        #pragma unroll
        for (int tm = 0; tm < 2; tm++)
            #pragma unroll
            for (int sl = 0; sl < 2; sl++) { psum[tm][sl] = 0.0f; psq[tm][sl] = 0.0f; }
        #pragma unroll
        for (int tm = 0; tm < 2; tm++) {
            #pragma unroll
            for (int tn = 0; tn < 8; tn++) {
                int col = wn * 64 + tn * 8 + gc;
                float bs0 = bp[col], bs1 = bp[col + 1];
                int lrow0 = wm * 32 + tm * 16 + gr;
                size_t grow0 = (size_t)(bR * 64 + lrow0);
                float2 r0 = *(const float2*)(resid + grow0 * CDIM + col);
                float2 r1 = *(const float2*)(resid + (grow0 + 8) * CDIM + col);
                float v0 = acc1[tm][tn][0] + bs0 + r0.x;
                float v1 = acc1[tm][tn][1] + bs1 + r0.y;
                float v2 = acc1[tm][tn][2] + bs0 + r1.x;
                float v3 = acc1[tm][tn][3] + bs1 + r1.y;
                acc1[tm][tn][0] = v0; acc1[tm][tn][1] = v1;
                acc1[tm][tn][2] = v2; acc1[tm][tn][3] = v3;
                *(float2*)(x1s + lrow0 * 136 + col) = make_float2(v0, v1);
                *(float2*)(x1s + (lrow0 + 8) * 136 + col) = make_float2(v2, v3);
                psum[tm][0] += v0 + v1;  psq[tm][0] += v0 * v0 + v1 * v1;
                psum[tm][1] += v2 + v3;  psq[tm][1] += v2 * v2 + v3 * v3;
            }
        }
        #pragma unroll
        for (int tm = 0; tm < 2; tm++)
            #pragma unroll
            for (int sl = 0; sl < 2; sl++) {
                float s = psum[tm][sl], q = psq[tm][sl];
                s += __shfl_xor_sync(0xFFFFFFFFu, s, 1); q += __shfl_xor_sync(0xFFFFFFFFu, q, 1);
                s += __shfl_xor_sync(0xFFFFFFFFu, s, 2); q += __shfl_xor_sync(0xFFFFFFFFu, q, 2);
                if ((lane & 3) == 0) red[wn * 64 + wm * 32 + tm * 16 + sl * 8 + gr] = make_float2(s, q);
            }
        __syncthreads();
        #pragma unroll
        for (int tm = 0; tm < 2; tm++) {
            #pragma unroll
            for (int sl = 0; sl < 2; sl++) {
                int lrow = wm * 32 + tm * 16 + sl * 8 + gr;
                float2 t0 = red[lrow], t1 = red[64 + lrow];
                float mu = (t0.x + t1.x) * (1.0f / 128.0f);
                float var = (t0.y + t1.y) * (1.0f / 128.0f) - mu * mu;
                float inv = rsqrtf(var + 1e-5f);
                #pragma unroll
                for (int tn = 0; tn < 8; tn++) {
                    int col = wn * 64 + tn * 8 + gc;
                    float v0 = acc1[tm][tn][sl * 2 + 0], v1 = acc1[tm][tn][sl * 2 + 1];
                    float n0 = (v0 - mu) * inv * g2[col] + b2[col];
                    float n1 = (v1 - mu) * inv * g2[col + 1] + b2[col + 1];
                    // xn2 -> A tiles, ldmatrix layout
                    *(uint32_t*)(smem + (col >> 6) * 9216 + lrow * 144 + ((col & 63) >> 3) * 16 + (col & 7) * 2)
                        = pack_bf2(n0, n1);
                }
            }
        }
        __syncthreads();   // xn2 ready
    }

    // ---- MLP: interleaved fc1(nt) -> h tile -> fc2 partial ----
    const float is2 = 0.70710678118654752f;
    for (int nt = 0; nt < 4; nt++) {
        float acc1[2][8][4];
        #pragma unroll
        for (int i = 0; i < 2; i++)
            #pragma unroll
            for (int j = 0; j < 8; j++)
                #pragma unroll
                for (int q = 0; q < 4; q++) acc1[i][j][q] = 0.0f;
        #pragma unroll
        for (int kt = 0; kt < 2; kt++) {
            int s = 2 + nt * 4 + kt;
            stepWait(s); __syncthreads();
            mma_tile(smem + kt * 9216, smem + MG_W0 + (s & 1) * 18432, wm, wn, lane, acc1);
            __syncthreads();
            if (s + 2 < 18) loadW(s + 2);
        }
        // h epilogue: gelu(acc1 + b1) -> h tile (bf16, ldmatrix layout)
        #pragma unroll
        for (int tm = 0; tm < 2; tm++) {
            #pragma unroll
            for (int tn = 0; tn < 8; tn++) {
                int col = wn * 64 + tn * 8 + gc;          // local 0..127
                int colg = nt * 128 + col;
                float bs0 = b1[colg], bs1 = b1[colg + 1];
                int lrow0 = wm * 32 + tm * 16 + gr;
                float v0 = acc1[tm][tn][0] + bs0, v1 = acc1[tm][tn][1] + bs1;
                float v2 = acc1[tm][tn][2] + bs0, v3 = acc1[tm][tn][3] + bs1;
                v0 = 0.5f * v0 * (1.0f + erff(v0 * is2));
                v1 = 0.5f * v1 * (1.0f + erff(v1 * is2));
                v2 = 0.5f * v2 * (1.0f + erff(v2 * is2));
                v3 = 0.5f * v3 * (1.0f + erff(v3 * is2));
                int boff = (col >> 6) * 9216 + ((col & 63) >> 3) * 16 + (col & 7) * 2;
                *(uint32_t*)(smem + MG_H0 + boff + lrow0 * 144)       = pack_bf2(v0, v1);
                *(uint32_t*)(smem + MG_H0 + boff + (lrow0 + 8) * 144) = pack_bf2(v2, v3);
            }
        }
        __syncthreads();   // h visible
        #pragma unroll
        for (int q = 0; q < 2; q++) {
            int s = 4 + nt * 4 + q;
            stepWait(s); __syncthreads();
            mma_tile(smem + MG_H0 + q * 9216, smem + MG_W0 + (s & 1) * 18432, wm, wn, lane, acc2);
            __syncthreads();
            if (s + 2 < 18) loadW(s + 2);
        }
    }

    // ---- final epilogue: out = acc2 + b2b + x1 ----
    #pragma unroll
    for (int tm = 0; tm < 2; tm++) {
        #pragma unroll
        for (int tn = 0; tn < 8; tn++) {
            int col = wn * 64 + tn * 8 + gc;
            float bs0 = b2b[col], bs1 = b2b[col + 1];
            int lrow0 = wm * 32 + tm * 16 + gr;
            size_t grow0 = (size_t)(bR * 64 + lrow0);
            float2 x0 = *(const float2*)(x1s + lrow0 * 136 + col);
            float2 x1v = *(const float2*)(x1s + (lrow0 + 8) * 136 + col);
            float v0 = acc2[tm][tn][0] + bs0, v1 = acc2[tm][tn][1] + bs1;
            float v2 = acc2[tm][tn][2] + bs0, v3 = acc2[tm][tn][3] + bs1;
            *(float2*)(out + grow0 * CDIM + col)       = make_float2(v0 + x0.x, v1 + x0.y);
            *(float2*)(out + (grow0 + 8) * CDIM + col) = make_float2(v2 + x1v.x, v3 + x1v.y);
        }
    }
}

// ---------------- tensor-core window attention, split-precision P@V ----------------
__global__ void __launch_bounds__(256)
attn_kernel(const __nv_bfloat16* __restrict__ qkv, const __nv_bfloat16* __restrict__ vlo,
            const float* __restrict__ rpb, __nv_bfloat16* __restrict__ outw) {
    extern __shared__ unsigned char sm[];
    const int widx = blockIdx.x;
    const int tid = threadIdx.x;

    #pragma unroll
    for (int it = 0; it < 12; it++) {
        int idx = it * 256 + tid;
        int c4 = idx & 3, row = (idx >> 2) & 63, h = (idx >> 8) & 3, t = idx >> 10;
        uint4 v = make_uint4(0, 0, 0, 0);
        if (row < 49)
            v = *(const uint4*)(qkv + (size_t)widx * 18816 + row * 384 + t * 128 + h * 32 + c4 * 8);
        *(uint4*)(sm + h * 15360 + t * 5120 + row * 80 + c4 * 16) = v;
    }
    #pragma unroll
    for (int it = 0; it < 4; it++) {
        int idx = it * 256 + tid;
        int c4 = idx & 3, row = (idx >> 2) & 63, h = idx >> 8;
        uint4 v = make_uint4(0, 0, 0, 0);
        if (row < 49)
            v = *(const uint4*)(vlo + ((size_t)widx * 49 + row) * 128 + h * 32 + c4 * 8);
        *(uint4*)(sm + 61440 + h * 5120 + row * 80 + c4 * 16) = v;
    }
    float* rp = (float*)(sm + 81920);
    for (int p = tid; p < 676; p += 256) rp[p] = rpb[(p % 169) * 4 + (p / 169)];
    int* regs = (int*)(sm + 84624);
    signed char* i2t = (signed char*)(sm + 84880);
    signed char* j2t = (signed char*)(sm + 84944);
    if (tid < 64) { i2t[tid] = tid / 7; j2t[tid] = tid % 7; }
    if (tid < 49) {
        int wi = widx & 63;
        int wh = wi >> 3, ww = wi & 7;
        int i = tid / 7, j = tid - i * 7;
        int grr = wh * 7 + i, gcc = ww * 7 + j;
        int rr = grr < 49 ? 0 : (grr < 53 ? 1 : 2);
        int rc = gcc < 49 ? 0 : (gcc < 53 ? 1 : 2);
        regs[tid] = rr * 3 + rc;
    }
    __syncthreads();

    const int warp = tid >> 5, lane = tid & 31;
    const int h = warp >> 1, half = warp & 1;
    const int mat = lane >> 3, l7 = lane & 7, gr = lane >> 2, gc = (lane & 3) * 2;
    const unsigned char* Q = sm + h * 15360;
    const unsigned char* Kp = Q + 5120;
    const unsigned char* Vp = Q + 10240;
    const unsigned char* Vl = sm + 61440 + h * 5120;

    float sacc[2][8][4];
    #pragma unroll
    for (int i = 0; i < 2; i++)
        #pragma unroll
        for (int j = 0; j < 8; j++)
            #pragma unroll
            for (int q = 0; q < 4; q++) sacc[i][j][q] = 0.0f;

    #pragma unroll
    for (int kc = 0; kc < 2; kc++) {
        uint32_t a[2][4];
        #pragma unroll
        for (int tm = 0; tm < 2; tm++)
            ldsm4(a[tm][0], a[tm][1], a[tm][2], a[tm][3],
                  (uint32_t)__cvta_generic_to_shared(Q + (half * 32 + tm * 16 + (mat & 1) * 8 + l7) * 80 + kc * 32 + (mat >> 1) * 16));
        uint32_t b[4][4];
        #pragma unroll
        for (int tn2 = 0; tn2 < 4; tn2++)
            ldsm4(b[tn2][0], b[tn2][1], b[tn2][2], b[tn2][3],
                  (uint32_t)__cvta_generic_to_shared(Kp + (tn2 * 16 + (mat >> 1) * 8 + l7) * 80 + kc * 32 + (mat & 1) * 16));
        #pragma unroll
        for (int tm = 0; tm < 2; tm++)
            #pragma unroll
            for (int tn = 0; tn < 8; tn++)
                mma16816(sacc[tm][tn], a[tm], b[tn >> 1][(tn & 1) * 2], b[tn >> 1][(tn & 1) * 2 + 1]);
    }

    const float scale = 0.17677669529663687f;
    uint32_t pa[2][4][4], pl[2][4][4];
    #pragma unroll
    for (int tm = 0; tm < 2; tm++) {
        #pragma unroll
        for (int slot = 0; slot < 2; slot++) {
            int n = half * 32 + tm * 16 + gr + slot * 8;
            bool valid = n < 49;
            int i1 = 0, j1 = 0, regn = 0;
            if (valid) { i1 = i2t[n]; j1 = j2t[n]; regn = regs[n]; }
            float vv[16];
            float mx = -1e30f;
            #pragma unroll
            for (int tn = 0; tn < 8; tn++) {
                #pragma unroll
                for (int e = 0; e < 2; e++) {
                    int m = tn * 8 + gc + e;
                    float v = -1e30f;
                    if (valid && m < 49) {
                        v = sacc[tm][tn][slot * 2 + e] * scale
                          + rp[h * 169 + (i1 - i2t[m] + 6) * 13 + (j1 - j2t[m] + 6)];
                        if (regs[m] != regn) v -= 100.0f;
                    }
                    vv[tn * 2 + e] = v;
                    mx = fmaxf(mx, v);
                }
            }
            mx = fmaxf(mx, __shfl_xor_sync(0xFFFFFFFFu, mx, 1));
            mx = fmaxf(mx, __shfl_xor_sync(0xFFFFFFFFu, mx, 2));
            float sum = 0.0f;
            #pragma unroll
            for (int i = 0; i < 16; i++) { vv[i] = __expf(vv[i] - mx); sum += vv[i]; }
            sum += __shfl_xor_sync(0xFFFFFFFFu, sum, 1);
            sum += __shfl_xor_sync(0xFFFFFFFFu, sum, 2);
            float inv = valid ? __frcp_rn(sum) : 0.0f;
            #pragma unroll
            for (int tn = 0; tn < 8; tn++) {
                float p0 = vv[tn * 2] * inv, p1 = vv[tn * 2 + 1] * inv;
                uint32_t u = pack_bf2(p0, p1);
                pa[tm][tn >> 1][(tn & 1) * 2 + slot] = u;
                float h0 = __uint_as_float(u << 16), h1 = __uint_as_float(u & 0xFFFF0000u);
                pl[tm][tn >> 1][(tn & 1) * 2 + slot] = pack_bf2(p0 - h0, p1 - h1);
            }
        }
    }

    float oacc[2][4][4];
    #pragma unroll
    for (int i = 0; i < 2; i++)
        #pragma unroll
        for (int j = 0; j < 4; j++)
            #pragma unroll
            for (int q = 0; q < 4; q++) oacc[i][j][q] = 0.0f;

    #pragma unroll
    for (int kk = 0; kk < 4; kk++) {
        uint32_t bh[2][4], bl[2][4];
        #pragma unroll
        for (int dd = 0; dd < 2; dd++) {
            ldsm4t(bh[dd][0], bh[dd][1], bh[dd][2], bh[dd][3],
                   (uint32_t)__cvta_generic_to_shared(Vp + (kk * 16 + (mat & 1) * 8 + l7) * 80 + dd * 32 + (mat >> 1) * 16));
            ldsm4t(bl[dd][0], bl[dd][1], bl[dd][2], bl[dd][3],
                   (uint32_t)__cvta_generic_to_shared(Vl + (kk * 16 + (mat & 1) * 8 + l7) * 80 + dd * 32 + (mat >> 1) * 16));
        }
        #pragma unroll
        for (int tm = 0; tm < 2; tm++) {
            #pragma unroll
            for (int dd = 0; dd < 2; dd++) {
                mma16816(oacc[tm][dd * 2 + 0], pa[tm][kk], bh[dd][0], bh[dd][1]);
                mma16816(oacc[tm][dd * 2 + 0], pl[tm][kk], bh[dd][0], bh[dd][1]);
                mma16816(oacc[tm][dd * 2 + 0], pa[tm][kk], bl[dd][0], bl[dd][1]);
                mma16816(oacc[tm][dd * 2 + 1], pa[tm][kk], bh[dd][2], bh[dd][3]);
                mma16816(oacc[tm][dd * 2 + 1], pl[tm][kk], bh[dd][2], bh[dd][3]);
                mma16816(oacc[tm][dd * 2 + 1], pa[tm][kk], bl[dd][2], bl[dd][3]);
            }
        }
    }

    #pragma unroll
    for (int tm = 0; tm < 2; tm++) {
        int n0 = half * 32 + tm * 16 + gr;
        #pragma unroll
        for (int dt = 0; dt < 4; dt++) {
            int col = h * 32 + dt * 8 + gc;
            if (n0 < 49)
                *(__nv_bfloat162*)(outw + ((size_t)widx * 49 + n0) * 128 + col) =
                    __floats2bfloat162_rn(oacc[tm][dt][0], oacc[tm][dt][1]);
            if (n0 + 8 < 49)
                *(__nv_bfloat162*)(outw + ((size_t)widx * 49 + n0 + 8) * 128 + col) =
                    __floats2bfloat162_rn(oacc[tm][dt][2], oacc[tm][dt][3]);
        }
    }
}

// ---------------- launch ----------------
#define FUSED_SMEM 73728
#define ATTN_SMEM 85008

extern "C" void kernel_launch(void* const* d_in, const int* in_sizes, int n_in,
                              void* d_out, int out_size) {
    const float* x      = (const float*)d_in[0];
    const float* n1g    = (const float*)d_in[1];
    const float* n1b    = (const float*)d_in[2];
    const float* qkv_w  = (const float*)d_in[3];
    const float* qkv_b  = (const float*)d_in[4];
    const float* proj_w = (const float*)d_in[5];
    const float* proj_b = (const float*)d_in[6];
    const float* rpb    = (const float*)d_in[7];
    const float* n2g    = (const float*)d_in[8];
    const float* n2b    = (const float*)d_in[9];
    const float* fc1_w  = (const float*)d_in[10];
    const float* fc1_b  = (const float*)d_in[11];
    const float* fc2_w  = (const float*)d_in[12];
    const float* fc2_b  = (const float*)d_in[13];
    float* out = (float*)d_out;

    __nv_bfloat16 *qkvb, *vlo, *attnb, *wq, *wp, *w1, *w2;
    cudaGetSymbolAddress((void**)&qkvb, g_qkv);
    cudaGetSymbolAddress((void**)&vlo,  g_vlo);
    cudaGetSymbolAddress((void**)&attnb,g_attn);
    cudaGetSymbolAddress((void**)&wq,   g_wq);
    cudaGetSymbolAddress((void**)&wp,   g_wp);
    cudaGetSymbolAddress((void**)&w1,   g_w1);
    cudaGetSymbolAddress((void**)&w2,   g_w2);

    cudaFuncSetAttribute((const void*)qkv_fused, cudaFuncAttributeMaxDynamicSharedMemorySize, FUSED_SMEM);
    cudaFuncSetAttribute((const void*)attn_kernel, cudaFuncAttributeMaxDynamicSharedMemorySize, ATTN_SMEM);
    cudaFuncSetAttribute((const void*)mlp_fused, cudaFuncAttributeMaxDynamicSharedMemorySize, MLP_SMEM);

    // 1. all weight conversions in one launch
    f2bf_all<<<192, 256>>>(qkv_w, proj_w, fc1_w, fc2_w, wq, wp, w1, w2);
    // 2. fused LN1 + shift/window gather + QKV GEMM -> bf16 qkv (+ V lo plane)
    qkv_fused<<<MROWS / 128, 256, FUSED_SMEM>>>(x, n1g, n1b, wq, qkv_b, qkvb, vlo);
    // 3. tensor-core window attention (split P/V) -> bf16
    attn_kernel<<<NWB, 256, ATTN_SMEM>>>(qkvb, vlo, rpb, attnb);
    // 4. fused proj + resid + LN2 + fc1 + GELU + fc2 + resid -> out (64-row CTAs, 2/SM)
    mlp_fused<<<MROWS / 64, 128, MLP_SMEM>>>(attnb, x, wp, proj_b, n2g, n2b,
                                             w1, fc1_b, w2, fc2_b, out);
}